// round 3
// baseline (speedup 1.0000x reference)
#include <cuda_runtime.h>
#include <math.h>

#define BATCH 16
#define N1D 1024
#define CCH 256

typedef unsigned long long ull;

// Scratch (device globals; no allocation allowed)
__device__ float g_p1[BATCH * N1D * CCH];      // 16.8 MB
__device__ float g_x2[BATCH * 256 * CCH];      // 4.2 MB
__device__ float g_x3[BATCH * 64 * CCH];       // 1.05 MB
__device__ float g_att2[BATCH * 256 * 256];    // 4.2 MB
__device__ float g_att3[BATCH * 64 * 64];      // 0.26 MB

// ---- packed fp32x2 helpers (FFMA2 path; ptxas never emits it from C++) ----
__device__ __forceinline__ void ffma2(ull& d, ull a, ull b) {
    asm("fma.rn.f32x2 %0, %1, %2, %0;" : "+l"(d) : "l"(a), "l"(b));
}
__device__ __forceinline__ ull pack2(float x) {
    ull r; asm("mov.b64 %0, {%1, %1};" : "=l"(r) : "f"(x)); return r;
}
__device__ __forceinline__ float2 unpack2(ull v) {
    float2 f; asm("mov.b64 {%0, %1}, %2;" : "=f"(f.x), "=f"(f.y) : "l"(v));
    return f;
}

// ---------------------------------------------------------------------------
// init rows of out to bias (for K-split atomic projections)
// ---------------------------------------------------------------------------
__global__ void init_bias_kernel(float* __restrict__ out,
                                 const float* __restrict__ bias)
{
    int idx = blockIdx.x * 256 + threadIdx.x;    // float4 index
    int cj = idx & 63;
    float4 bv = *(const float4*)&bias[cj * 4];
    *(float4*)&out[idx * 4] = bv;
}

// ---------------------------------------------------------------------------
// Projection: out[M,256] = A[M,KDIM] @ W[KDIM,256] (+ bias), FFMA2 inner
// ---------------------------------------------------------------------------
__global__ __launch_bounds__(256) void proj_kernel(
    const float* __restrict__ A, const float* __restrict__ W,
    const float* __restrict__ bias, float* __restrict__ out, int KDIM)
{
    __shared__ float As[32 * 68];
    __shared__ float Ws[32 * 256];
    const int t  = threadIdx.x;
    const int ty = t >> 4, tx = t & 15;
    const int r0 = ty * 4;
    const int row0 = blockIdx.x * 64;
    const int kd    = KDIM / gridDim.y;
    const int kbase = blockIdx.y * kd;

    ulonglong2 acc[4][4];
#pragma unroll
    for (int i = 0; i < 4; i++)
#pragma unroll
        for (int q = 0; q < 4; q++) { acc[i][q].x = 0ULL; acc[i][q].y = 0ULL; }

    for (int k0 = 0; k0 < kd; k0 += 32) {
        const int kb = kbase + k0;
#pragma unroll
        for (int s = 0; s < 2; s++) {
            int lin = t + 256 * s;
            int row = lin >> 3, kc = lin & 7;
            float4 v = *(const float4*)&A[(size_t)(row0 + row) * KDIM + kb + kc * 4];
            As[(kc * 4 + 0) * 68 + row] = v.x;
            As[(kc * 4 + 1) * 68 + row] = v.y;
            As[(kc * 4 + 2) * 68 + row] = v.z;
            As[(kc * 4 + 3) * 68 + row] = v.w;
        }
#pragma unroll
        for (int s = 0; s < 8; s++) {
            int lin = t + 256 * s;
            int k = lin >> 6, ck = lin & 63;
            float4 v = *(const float4*)&W[(size_t)(kb + k) * CCH + ck * 4];
            *(float4*)&Ws[k * 256 + ck * 4] = v;
        }
        __syncthreads();
#pragma unroll 4
        for (int k = 0; k < 32; k++) {
            float4 a4 = *(const float4*)&As[k * 68 + r0];
            ull p0 = pack2(a4.x), p1 = pack2(a4.y);
            ull p2 = pack2(a4.z), p3 = pack2(a4.w);
#pragma unroll
            for (int q = 0; q < 4; q++) {
                ulonglong2 w2 = *(const ulonglong2*)&Ws[k * 256 + (tx + 16 * q) * 4];
                ffma2(acc[0][q].x, p0, w2.x); ffma2(acc[0][q].y, p0, w2.y);
                ffma2(acc[1][q].x, p1, w2.x); ffma2(acc[1][q].y, p1, w2.y);
                ffma2(acc[2][q].x, p2, w2.x); ffma2(acc[2][q].y, p2, w2.y);
                ffma2(acc[3][q].x, p3, w2.x); ffma2(acc[3][q].y, p3, w2.y);
            }
        }
        __syncthreads();
    }

    if (gridDim.y == 1) {
#pragma unroll
        for (int q = 0; q < 4; q++) {
            float4 bv = *(const float4*)&bias[(tx + 16 * q) * 4];
#pragma unroll
            for (int i = 0; i < 4; i++) {
                float2 lo = unpack2(acc[i][q].x), hi = unpack2(acc[i][q].y);
                float4 o;
                o.x = lo.x + bv.x; o.y = lo.y + bv.y;
                o.z = hi.x + bv.z; o.w = hi.y + bv.w;
                *(float4*)&out[(size_t)(row0 + r0 + i) * CCH + (tx + 16 * q) * 4] = o;
            }
        }
    } else {
#pragma unroll
        for (int q = 0; q < 4; q++)
#pragma unroll
            for (int i = 0; i < 4; i++) {
                float2 lo = unpack2(acc[i][q].x), hi = unpack2(acc[i][q].y);
                float* dst = &out[(size_t)(row0 + r0 + i) * CCH + (tx + 16 * q) * 4];
                atomicAdd(dst + 0, lo.x);
                atomicAdd(dst + 1, lo.y);
                atomicAdd(dst + 2, hi.x);
                atomicAdd(dst + 3, hi.y);
            }
    }
}

// ---------------------------------------------------------------------------
// Gram 128x128 tile (att2), FFMA2 inner
// ---------------------------------------------------------------------------
__global__ __launch_bounds__(256) void gram128_kernel(
    const float* __restrict__ X, float* __restrict__ out, int N)
{
    __shared__ float At[16 * 132];
    __shared__ float Bt[16 * 132];
    const int b  = blockIdx.z;
    const int i0 = blockIdx.x * 128, j0 = blockIdx.y * 128;
    const int t  = threadIdx.x;
    const int ty = t >> 4, tx = t & 15;
    const int ra = ty * 4, ca = tx * 4;
    const float* Xb = X + (size_t)b * N * CCH;

    ulonglong2 acc[8][2];
#pragma unroll
    for (int i = 0; i < 8; i++)
#pragma unroll
        for (int j = 0; j < 2; j++) { acc[i][j].x = 0ULL; acc[i][j].y = 0ULL; }

    for (int k0 = 0; k0 < CCH; k0 += 16) {
#pragma unroll
        for (int s = 0; s < 2; s++) {
            int lin = t + 256 * s;
            int row = lin >> 2, kc = lin & 3;
            float4 va = *(const float4*)&Xb[(size_t)(i0 + row) * CCH + k0 + kc * 4];
            At[(kc * 4 + 0) * 132 + row] = va.x;
            At[(kc * 4 + 1) * 132 + row] = va.y;
            At[(kc * 4 + 2) * 132 + row] = va.z;
            At[(kc * 4 + 3) * 132 + row] = va.w;
            float4 vb = *(const float4*)&Xb[(size_t)(j0 + row) * CCH + k0 + kc * 4];
            Bt[(kc * 4 + 0) * 132 + row] = vb.x;
            Bt[(kc * 4 + 1) * 132 + row] = vb.y;
            Bt[(kc * 4 + 2) * 132 + row] = vb.z;
            Bt[(kc * 4 + 3) * 132 + row] = vb.w;
        }
        __syncthreads();
#pragma unroll 4
        for (int k = 0; k < 16; k++) {
            float4 a0 = *(const float4*)&At[k * 132 + ra];
            float4 a1 = *(const float4*)&At[k * 132 + 64 + ra];
            ulonglong2 b0 = *(const ulonglong2*)&Bt[k * 132 + ca];
            ulonglong2 b1 = *(const ulonglong2*)&Bt[k * 132 + 64 + ca];
            ull pav[8] = {pack2(a0.x), pack2(a0.y), pack2(a0.z), pack2(a0.w),
                          pack2(a1.x), pack2(a1.y), pack2(a1.z), pack2(a1.w)};
#pragma unroll
            for (int i = 0; i < 8; i++) {
                ffma2(acc[i][0].x, pav[i], b0.x);
                ffma2(acc[i][0].y, pav[i], b0.y);
                ffma2(acc[i][1].x, pav[i], b1.x);
                ffma2(acc[i][1].y, pav[i], b1.y);
            }
        }
        __syncthreads();
    }

#pragma unroll
    for (int hr = 0; hr < 2; hr++)
#pragma unroll
        for (int i = 0; i < 4; i++) {
            int row = i0 + hr * 64 + ra + i;
            float2 l0 = unpack2(acc[hr*4+i][0].x), h0 = unpack2(acc[hr*4+i][0].y);
            float2 l1 = unpack2(acc[hr*4+i][1].x), h1 = unpack2(acc[hr*4+i][1].y);
            float4 o0 = make_float4(l0.x, l0.y, h0.x, h0.y);
            float4 o1 = make_float4(l1.x, l1.y, h1.x, h1.y);
            *(float4*)&out[(size_t)b * N * N + (size_t)row * N + j0 + ca]      = o0;
            *(float4*)&out[(size_t)b * N * N + (size_t)row * N + j0 + 64 + ca] = o1;
        }
}

// ---------------------------------------------------------------------------
// Gram 64x64 (att3 only; tiny)
// ---------------------------------------------------------------------------
__global__ __launch_bounds__(256) void attnt_kernel(
    const float* __restrict__ X, float* __restrict__ out, int N)
{
    __shared__ float Ai[32][65];
    __shared__ float Bj[32][65];
    const int b  = blockIdx.z;
    const int i0 = blockIdx.x * 64, j0 = blockIdx.y * 64;
    const int t  = threadIdx.x;
    const int ty = t >> 4, tx = t & 15;
    const int r0 = ty * 4, c0 = tx * 4;
    const float* Xb = X + (size_t)b * N * CCH;

    float acc[4][4] = {};

    for (int k0 = 0; k0 < CCH; k0 += 32) {
#pragma unroll
        for (int i = 0; i < 8; i++) {
            int lin = t + 256 * i;
            int r = lin >> 5, k = lin & 31;
            Ai[k][r] = Xb[(size_t)(i0 + r) * CCH + k0 + k];
            Bj[k][r] = Xb[(size_t)(j0 + r) * CCH + k0 + k];
        }
        __syncthreads();
#pragma unroll
        for (int k = 0; k < 32; k++) {
            float a[4], bb[4];
#pragma unroll
            for (int i = 0; i < 4; i++) a[i]  = Ai[k][r0 + i];
#pragma unroll
            for (int j = 0; j < 4; j++) bb[j] = Bj[k][c0 + j];
#pragma unroll
            for (int i = 0; i < 4; i++)
#pragma unroll
                for (int j = 0; j < 4; j++)
                    acc[i][j] += a[i] * bb[j];
        }
        __syncthreads();
    }

#pragma unroll
    for (int i = 0; i < 4; i++) {
        float4 o;
        o.x = acc[i][0]; o.y = acc[i][1]; o.z = acc[i][2]; o.w = acc[i][3];
        *(float4*)&out[(size_t)b * N * N + (size_t)(i0 + r0 + i) * N + j0 + c0] = o;
    }
}

// ---------------------------------------------------------------------------
// Fused sigmoid-attention, FFMA2 + broadcast warp layout.
// lanes = n rows (l, l+32); warps = m / chunk columns.
// n-tile 64, m-tile 128, K channel-halved (Ks = 128 rows x 128 ch).
// ---------------------------------------------------------------------------

#define STAGE_K(m0_, h_) do {                                                  \
    _Pragma("unroll")                                                          \
    for (int s_ = 0; s_ < 16; s_++) {                                          \
        int lin_ = t + 256 * s_;                                               \
        int row_ = lin_ >> 5, ck_ = lin_ & 31;                                 \
        float4 v_ = *(const float4*)(p1b + (size_t)((m0_) + row_) * CCH +      \
                                     (h_) * 128 + ck_ * 4);                    \
        *(float4*)(Ks + row_ * 128 + (((ck_) ^ (row_ & 15)) << 2)) = v_;       \
    }                                                                          \
} while (0)

#define GEMM2_PASS(H_) do {                                                    \
    _Pragma("unroll 2")                                                        \
    for (int m_ = 0; m_ < 128; m_++) {                                         \
        ull pa_ = pack2(SsA[m_]);                                              \
        ull pb_ = pack2(SsB[m_]);                                              \
        _Pragma("unroll")                                                      \
        for (int q_ = 0; q_ < 4; q_++) {                                       \
            ulonglong2 kv_ = *(const ulonglong2*)(Ks + m_ * 128 +              \
                                (((w * 4 + q_) ^ (m_ & 15)) << 2));            \
            ffma2(ObA[H_][q_].x, pa_, kv_.x);                                  \
            ffma2(ObA[H_][q_].y, pa_, kv_.y);                                  \
            ffma2(ObB[H_][q_].x, pb_, kv_.x);                                  \
            ffma2(ObB[H_][q_].y, pb_, kv_.y);                                  \
        }                                                                      \
    }                                                                          \
} while (0)

__global__ __launch_bounds__(256, 1) void fused_kernel(
    const float* __restrict__ p1,
    const float* __restrict__ att2, const float* __restrict__ att3,
    const float* __restrict__ pa1, const float* __restrict__ pa2,
    const float* __restrict__ pa3, float* __restrict__ out)
{
    extern __shared__ float sm[];
    float* Qs = sm;                   // 64 x 256 ch (64 chunks), swizzled
    float* Ks = Qs + 64 * 256;        // 128 x 128 ch (32 chunks), swizzled
    float* Ss = Ks + 128 * 128;       // 64 x 133
    float* A2 = Ss + 64 * 133;        // 17 x 257 (padded)
    float* A3 = A2 + 17 * 257;        // 5 x 65  (padded)

    const int b  = blockIdx.y;
    const int n0 = blockIdx.x * 64;
    const int t  = threadIdx.x;
    const int w  = t >> 5, l = t & 31;
    const int sq = l & 15;            // swizzle key for both rows l, l+32

    const float* p1b = p1 + (size_t)b * N1D * CCH;
    const float sa1 = *pa1, sa2 = *pa2, sa3 = *pa3;
    const int r2lo = n0 >> 2;
    const int r3lo = n0 >> 4;

    // ---- stage Q tile (64 x 256), swizzled ----
#pragma unroll
    for (int i = 0; i < 16; i++) {
        int lin = t + 256 * i;
        int row = lin >> 6, ck = lin & 63;
        float4 v = *(const float4*)(p1b + (size_t)(n0 + row) * CCH + ck * 4);
        *(float4*)(Qs + row * 256 + ((ck ^ (row & 15)) << 2)) = v;
    }
    // ---- stage att2 window 17x256 (stride 257) ----
    for (int lin = t; lin < 17 * 256; lin += 256) {
        int rr = lin >> 8, cc = lin & 255;
        int src_r = min(r2lo + rr, 255);
        A2[rr * 257 + cc] = att2[((size_t)b * 256 + src_r) * 256 + cc];
    }
    // ---- stage att3 window 5x64 (stride 65) ----
    for (int lin = t; lin < 5 * 64; lin += 256) {
        int rr = lin >> 6, cc = lin & 63;
        int src_r = min(r3lo + rr, 63);
        A3[rr * 65 + cc] = att3[((size_t)b * 64 + src_r) * 64 + cc];
    }

    // per-row constants (rows na = n0+l, nb = na+32); fn/fn3 identical for both
    const int   na  = n0 + l;
    const int   rna = na >> 2;
    const float fn  = (float)(na & 3) * 0.25f;
    const float fn3 = (float)(na & 15) * 0.0625f;
    const float* Ar0a = A2 + (rna - r2lo) * 257;
    const float* Ar1a = A2 + (min(rna + 1, 255) - r2lo) * 257;
    const float* Ar0b = A2 + (rna + 8 - r2lo) * 257;
    const float* Ar1b = A2 + (min(rna + 9, 255) - r2lo) * 257;
    const int   rn3  = na >> 4;
    const float* Br0a = A3 + (rn3 - r3lo) * 65;
    const float* Br1a = A3 + (min(rn3 + 1, 63) - r3lo) * 65;
    const float* Br0b = A3 + (rn3 + 2 - r3lo) * 65;
    const float* Br1b = A3 + (min(rn3 + 3, 63) - r3lo) * 65;
    float* SsA = Ss + l * 133;
    float* SsB = Ss + (l + 32) * 133;

    ulonglong2 ObA[2][4], ObB[2][4];
#pragma unroll
    for (int h = 0; h < 2; h++)
#pragma unroll
        for (int q = 0; q < 4; q++) {
            ObA[h][q].x = 0ULL; ObA[h][q].y = 0ULL;
            ObB[h][q].x = 0ULL; ObB[h][q].y = 0ULL;
        }

    for (int mt = 0; mt < 8; mt++) {
        const int m0 = mt * 128;
        ull accA[16], accB[16];
#pragma unroll
        for (int j = 0; j < 16; j++) { accA[j] = 0ULL; accB[j] = 0ULL; }

        // ---- GEMM1: S = Q . K^T, two channel halves ----
#pragma unroll 1
        for (int h = 0; h < 2; h++) {
            __syncthreads();           // prior readers of Ks done
            STAGE_K(m0, h);
            __syncthreads();
#pragma unroll 2
            for (int ck = 0; ck < 32; ck++) {
                const int cq = h * 32 + ck;
                ulonglong2 qa = *(const ulonglong2*)(Qs + l * 256 + ((cq ^ sq) << 2));
                ulonglong2 qb = *(const ulonglong2*)(Qs + (l + 32) * 256 + ((cq ^ sq) << 2));
#pragma unroll
                for (int j = 0; j < 16; j++) {
                    ulonglong2 kv = *(const ulonglong2*)(Ks + (w * 16 + j) * 128 +
                                                         ((ck ^ j) << 2));
                    ffma2(accA[j], qa.x, kv.x);
                    ffma2(accA[j], qa.y, kv.y);
                    ffma2(accB[j], qb.x, kv.x);
                    ffma2(accB[j], qb.y, kv.y);
                }
            }
        }

        // ---- epilogue: gating lerp + sigmoid -> Ss ----
#pragma unroll
        for (int j = 0; j < 16; j++) {
            const int m  = m0 + w * 16 + j;
            const int rm = m >> 2;
            const float fm = (float)(m & 3) * 0.25f;
            const int c21 = min(rm + 1, 255);
            const int rm3 = m >> 4;
            const float fm3 = (float)(m & 15) * 0.0625f;
            const int c31 = min(rm3 + 1, 63);

            float h00 = (1.f - fm) * Ar0a[rm] + fm * Ar0a[c21];
            float h01 = (1.f - fm) * Ar1a[rm] + fm * Ar1a[c21];
            float h10 = (1.f - fm) * Ar0b[rm] + fm * Ar0b[c21];
            float h11 = (1.f - fm) * Ar1b[rm] + fm * Ar1b[c21];
            float v2a = (1.f - fn) * h00 + fn * h01;
            float v2b = (1.f - fn) * h10 + fn * h11;

            float g00 = (1.f - fm3) * Br0a[rm3] + fm3 * Br0a[c31];
            float g01 = (1.f - fm3) * Br1a[rm3] + fm3 * Br1a[c31];
            float g10 = (1.f - fm3) * Br0b[rm3] + fm3 * Br0b[c31];
            float g11 = (1.f - fm3) * Br1b[rm3] + fm3 * Br1b[c31];
            float v3a = (1.f - fn3) * g00 + fn3 * g01;
            float v3b = (1.f - fn3) * g10 + fn3 * g11;

            float2 fa = unpack2(accA[j]);
            float2 fb = unpack2(accB[j]);
            float va = sa1 * (fa.x + fa.y) + sa2 * v2a + sa3 * v3a;
            float vb = sa1 * (fb.x + fb.y) + sa2 * v2b + sa3 * v3b;
            SsA[w * 16 + j] = 1.0f / (1.0f + __expf(-va));
            SsB[w * 16 + j] = 1.0f / (1.0f + __expf(-vb));
        }
        __syncthreads();               // Ss visible; Ks still holds half 1

        // ---- GEMM2 half 1 (chunks 32..63) ----
        GEMM2_PASS(1);
        __syncthreads();
        STAGE_K(m0, 0);                // restage half 0
        __syncthreads();
        // ---- GEMM2 half 0 (chunks 0..31) ----
        GEMM2_PASS(0);
    }

    // ---- final: out = O + p1 (p1 resident in Qs) ----
    float* orowA = out + ((size_t)(b * N1D + n0 + l)) * CCH;
    float* orowB = out + ((size_t)(b * N1D + n0 + l + 32)) * CCH;
#pragma unroll
    for (int h = 0; h < 2; h++)
#pragma unroll
        for (int q = 0; q < 4; q++) {
            const int c = h * 32 + w * 4 + q;
            float4 pva = *(const float4*)(Qs + l * 256 + ((c ^ sq) << 2));
            float4 pvb = *(const float4*)(Qs + (l + 32) * 256 + ((c ^ sq) << 2));
            float2 la = unpack2(ObA[h][q].x), ha = unpack2(ObA[h][q].y);
            float2 lb = unpack2(ObB[h][q].x), hb = unpack2(ObB[h][q].y);
            float4 oa = make_float4(la.x + pva.x, la.y + pva.y,
                                    ha.x + pva.z, ha.y + pva.w);
            float4 ob = make_float4(lb.x + pvb.x, lb.y + pvb.y,
                                    hb.x + pvb.z, hb.y + pvb.w);
            *(float4*)(orowA + c * 4) = oa;
            *(float4*)(orowB + c * 4) = ob;
        }
}

// ---------------------------------------------------------------------------
extern "C" void kernel_launch(void* const* d_in, const int* in_sizes, int n_in,
                              void* d_out, int out_size)
{
    const float* f1 = (const float*)d_in[0];
    const float* f2 = (const float*)d_in[1];
    const float* f3 = (const float*)d_in[2];
    const float* w1 = (const float*)d_in[3];
    const float* b1 = (const float*)d_in[4];
    const float* w2 = (const float*)d_in[5];
    const float* b2 = (const float*)d_in[6];
    const float* w3 = (const float*)d_in[7];
    const float* b3 = (const float*)d_in[8];
    const float* a1 = (const float*)d_in[9];
    const float* a2 = (const float*)d_in[10];
    const float* a3 = (const float*)d_in[11];
    float* out = (float*)d_out;

    float *p1, *x2, *x3, *att2, *att3;
    cudaGetSymbolAddress((void**)&p1,   g_p1);
    cudaGetSymbolAddress((void**)&x2,   g_x2);
    cudaGetSymbolAddress((void**)&x3,   g_x3);
    cudaGetSymbolAddress((void**)&att2, g_att2);
    cudaGetSymbolAddress((void**)&att3, g_att3);

    // bias pre-init for K-split projections
    init_bias_kernel<<<(BATCH * 256 * CCH) / 1024, 256>>>(x2, b2);
    init_bias_kernel<<<(BATCH * 64  * CCH) / 1024, 256>>>(x3, b3);

    // 1x1 conv projections
    proj_kernel<<<dim3((BATCH * N1D) / 64, 1), 256>>>(f1, w1, b1, p1, 256);
    proj_kernel<<<dim3((BATCH * 256) / 64, 2), 256>>>(f2, w2, b2, x2, 512);
    proj_kernel<<<dim3((BATCH * 64)  / 64, 4), 256>>>(f3, w3, b3, x3, 1024);

    // small Gram matrices
    gram128_kernel<<<dim3(2, 2, BATCH), 256>>>(x2, att2, 256);
    attnt_kernel<<<dim3(1, 1, BATCH), 256>>>(x3, att3, 64);

    // fused sigmoid-attention + output
    const int smem_bytes = (64 * 256 + 128 * 128 + 64 * 133 + 17 * 257 + 5 * 65) * 4;
    cudaFuncSetAttribute(fused_kernel,
                         cudaFuncAttributeMaxDynamicSharedMemorySize, smem_bytes);
    fused_kernel<<<dim3(16, BATCH), 256, smem_bytes>>>(p1, att2, att3,
                                                       a1, a2, a3, out);
}

// round 4
// speedup vs baseline: 1.0001x; 1.0001x over previous
#include <cuda_runtime.h>
#include <math.h>

#define BATCH 16
#define N1D 1024
#define CCH 256

typedef unsigned long long ull;

// Scratch (device globals; no allocation allowed)
__device__ float g_p1[BATCH * N1D * CCH];      // 16.8 MB
__device__ float g_x2[BATCH * 256 * CCH];      // 4.2 MB
__device__ float g_x3[BATCH * 64 * CCH];       // 1.05 MB
__device__ float g_att2[BATCH * 256 * 256];    // 4.2 MB
__device__ float g_att3[BATCH * 64 * 64];      // 0.26 MB

// ---- packed fp32x2 helpers (FFMA2 path; ptxas never emits it from C++) ----
__device__ __forceinline__ void ffma2(ull& d, ull a, ull b) {
    asm("fma.rn.f32x2 %0, %1, %2, %0;" : "+l"(d) : "l"(a), "l"(b));
}
__device__ __forceinline__ ull pack2(float x) {
    ull r; asm("mov.b64 %0, {%1, %1};" : "=l"(r) : "f"(x)); return r;
}
__device__ __forceinline__ float2 unpack2(ull v) {
    float2 f; asm("mov.b64 {%0, %1}, %2;" : "=f"(f.x), "=f"(f.y) : "l"(v));
    return f;
}

// ---------------------------------------------------------------------------
// init rows of out to bias (for K-split atomic projections)
// ---------------------------------------------------------------------------
__global__ void init_bias_kernel(float* __restrict__ out,
                                 const float* __restrict__ bias)
{
    int idx = blockIdx.x * 256 + threadIdx.x;    // float4 index
    int cj = idx & 63;
    float4 bv = *(const float4*)&bias[cj * 4];
    *(float4*)&out[idx * 4] = bv;
}

// ---------------------------------------------------------------------------
// Projection: out[M,256] = A[M,KDIM] @ W[KDIM,256] (+ bias), FFMA2 inner
// ---------------------------------------------------------------------------
__global__ __launch_bounds__(256) void proj_kernel(
    const float* __restrict__ A, const float* __restrict__ W,
    const float* __restrict__ bias, float* __restrict__ out, int KDIM)
{
    __shared__ float As[32 * 68];
    __shared__ float Ws[32 * 256];
    const int t  = threadIdx.x;
    const int ty = t >> 4, tx = t & 15;
    const int r0 = ty * 4;
    const int row0 = blockIdx.x * 64;
    const int kd    = KDIM / gridDim.y;
    const int kbase = blockIdx.y * kd;

    ulonglong2 acc[4][4];
#pragma unroll
    for (int i = 0; i < 4; i++)
#pragma unroll
        for (int q = 0; q < 4; q++) { acc[i][q].x = 0ULL; acc[i][q].y = 0ULL; }

    for (int k0 = 0; k0 < kd; k0 += 32) {
        const int kb = kbase + k0;
#pragma unroll
        for (int s = 0; s < 2; s++) {
            int lin = t + 256 * s;
            int row = lin >> 3, kc = lin & 7;
            float4 v = *(const float4*)&A[(size_t)(row0 + row) * KDIM + kb + kc * 4];
            As[(kc * 4 + 0) * 68 + row] = v.x;
            As[(kc * 4 + 1) * 68 + row] = v.y;
            As[(kc * 4 + 2) * 68 + row] = v.z;
            As[(kc * 4 + 3) * 68 + row] = v.w;
        }
#pragma unroll
        for (int s = 0; s < 8; s++) {
            int lin = t + 256 * s;
            int k = lin >> 6, ck = lin & 63;
            float4 v = *(const float4*)&W[(size_t)(kb + k) * CCH + ck * 4];
            *(float4*)&Ws[k * 256 + ck * 4] = v;
        }
        __syncthreads();
#pragma unroll 4
        for (int k = 0; k < 32; k++) {
            float4 a4 = *(const float4*)&As[k * 68 + r0];
            ull p0 = pack2(a4.x), p1 = pack2(a4.y);
            ull p2 = pack2(a4.z), p3 = pack2(a4.w);
#pragma unroll
            for (int q = 0; q < 4; q++) {
                ulonglong2 w2 = *(const ulonglong2*)&Ws[k * 256 + (tx + 16 * q) * 4];
                ffma2(acc[0][q].x, p0, w2.x); ffma2(acc[0][q].y, p0, w2.y);
                ffma2(acc[1][q].x, p1, w2.x); ffma2(acc[1][q].y, p1, w2.y);
                ffma2(acc[2][q].x, p2, w2.x); ffma2(acc[2][q].y, p2, w2.y);
                ffma2(acc[3][q].x, p3, w2.x); ffma2(acc[3][q].y, p3, w2.y);
            }
        }
        __syncthreads();
    }

    if (gridDim.y == 1) {
#pragma unroll
        for (int q = 0; q < 4; q++) {
            float4 bv = *(const float4*)&bias[(tx + 16 * q) * 4];
#pragma unroll
            for (int i = 0; i < 4; i++) {
                float2 lo = unpack2(acc[i][q].x), hi = unpack2(acc[i][q].y);
                float4 o;
                o.x = lo.x + bv.x; o.y = lo.y + bv.y;
                o.z = hi.x + bv.z; o.w = hi.y + bv.w;
                *(float4*)&out[(size_t)(row0 + r0 + i) * CCH + (tx + 16 * q) * 4] = o;
            }
        }
    } else {
#pragma unroll
        for (int q = 0; q < 4; q++)
#pragma unroll
            for (int i = 0; i < 4; i++) {
                float2 lo = unpack2(acc[i][q].x), hi = unpack2(acc[i][q].y);
                float* dst = &out[(size_t)(row0 + r0 + i) * CCH + (tx + 16 * q) * 4];
                atomicAdd(dst + 0, lo.x);
                atomicAdd(dst + 1, lo.y);
                atomicAdd(dst + 2, hi.x);
                atomicAdd(dst + 3, hi.y);
            }
    }
}

// ---------------------------------------------------------------------------
// Gram 128x128 tile (att2), FFMA2 inner
// ---------------------------------------------------------------------------
__global__ __launch_bounds__(256) void gram128_kernel(
    const float* __restrict__ X, float* __restrict__ out, int N)
{
    __shared__ float At[16 * 132];
    __shared__ float Bt[16 * 132];
    const int b  = blockIdx.z;
    const int i0 = blockIdx.x * 128, j0 = blockIdx.y * 128;
    const int t  = threadIdx.x;
    const int ty = t >> 4, tx = t & 15;
    const int ra = ty * 4, ca = tx * 4;
    const float* Xb = X + (size_t)b * N * CCH;

    ulonglong2 acc[8][2];
#pragma unroll
    for (int i = 0; i < 8; i++)
#pragma unroll
        for (int j = 0; j < 2; j++) { acc[i][j].x = 0ULL; acc[i][j].y = 0ULL; }

    for (int k0 = 0; k0 < CCH; k0 += 16) {
#pragma unroll
        for (int s = 0; s < 2; s++) {
            int lin = t + 256 * s;
            int row = lin >> 2, kc = lin & 3;
            float4 va = *(const float4*)&Xb[(size_t)(i0 + row) * CCH + k0 + kc * 4];
            At[(kc * 4 + 0) * 132 + row] = va.x;
            At[(kc * 4 + 1) * 132 + row] = va.y;
            At[(kc * 4 + 2) * 132 + row] = va.z;
            At[(kc * 4 + 3) * 132 + row] = va.w;
            float4 vb = *(const float4*)&Xb[(size_t)(j0 + row) * CCH + k0 + kc * 4];
            Bt[(kc * 4 + 0) * 132 + row] = vb.x;
            Bt[(kc * 4 + 1) * 132 + row] = vb.y;
            Bt[(kc * 4 + 2) * 132 + row] = vb.z;
            Bt[(kc * 4 + 3) * 132 + row] = vb.w;
        }
        __syncthreads();
#pragma unroll 4
        for (int k = 0; k < 16; k++) {
            float4 a0 = *(const float4*)&At[k * 132 + ra];
            float4 a1 = *(const float4*)&At[k * 132 + 64 + ra];
            ulonglong2 b0 = *(const ulonglong2*)&Bt[k * 132 + ca];
            ulonglong2 b1 = *(const ulonglong2*)&Bt[k * 132 + 64 + ca];
            ull pav[8] = {pack2(a0.x), pack2(a0.y), pack2(a0.z), pack2(a0.w),
                          pack2(a1.x), pack2(a1.y), pack2(a1.z), pack2(a1.w)};
#pragma unroll
            for (int i = 0; i < 8; i++) {
                ffma2(acc[i][0].x, pav[i], b0.x);
                ffma2(acc[i][0].y, pav[i], b0.y);
                ffma2(acc[i][1].x, pav[i], b1.x);
                ffma2(acc[i][1].y, pav[i], b1.y);
            }
        }
        __syncthreads();
    }

#pragma unroll
    for (int hr = 0; hr < 2; hr++)
#pragma unroll
        for (int i = 0; i < 4; i++) {
            int row = i0 + hr * 64 + ra + i;
            float2 l0 = unpack2(acc[hr*4+i][0].x), h0 = unpack2(acc[hr*4+i][0].y);
            float2 l1 = unpack2(acc[hr*4+i][1].x), h1 = unpack2(acc[hr*4+i][1].y);
            float4 o0 = make_float4(l0.x, l0.y, h0.x, h0.y);
            float4 o1 = make_float4(l1.x, l1.y, h1.x, h1.y);
            *(float4*)&out[(size_t)b * N * N + (size_t)row * N + j0 + ca]      = o0;
            *(float4*)&out[(size_t)b * N * N + (size_t)row * N + j0 + 64 + ca] = o1;
        }
}

// ---------------------------------------------------------------------------
// Gram 64x64 (att3 only; tiny)
// ---------------------------------------------------------------------------
__global__ __launch_bounds__(256) void attnt_kernel(
    const float* __restrict__ X, float* __restrict__ out, int N)
{
    __shared__ float Ai[32][65];
    __shared__ float Bj[32][65];
    const int b  = blockIdx.z;
    const int i0 = blockIdx.x * 64, j0 = blockIdx.y * 64;
    const int t  = threadIdx.x;
    const int ty = t >> 4, tx = t & 15;
    const int r0 = ty * 4, c0 = tx * 4;
    const float* Xb = X + (size_t)b * N * CCH;

    float acc[4][4] = {};

    for (int k0 = 0; k0 < CCH; k0 += 32) {
#pragma unroll
        for (int i = 0; i < 8; i++) {
            int lin = t + 256 * i;
            int r = lin >> 5, k = lin & 31;
            Ai[k][r] = Xb[(size_t)(i0 + r) * CCH + k0 + k];
            Bj[k][r] = Xb[(size_t)(j0 + r) * CCH + k0 + k];
        }
        __syncthreads();
#pragma unroll
        for (int k = 0; k < 32; k++) {
            float a[4], bb[4];
#pragma unroll
            for (int i = 0; i < 4; i++) a[i]  = Ai[k][r0 + i];
#pragma unroll
            for (int j = 0; j < 4; j++) bb[j] = Bj[k][c0 + j];
#pragma unroll
            for (int i = 0; i < 4; i++)
#pragma unroll
                for (int j = 0; j < 4; j++)
                    acc[i][j] += a[i] * bb[j];
        }
        __syncthreads();
    }

#pragma unroll
    for (int i = 0; i < 4; i++) {
        float4 o;
        o.x = acc[i][0]; o.y = acc[i][1]; o.z = acc[i][2]; o.w = acc[i][3];
        *(float4*)&out[(size_t)b * N * N + (size_t)(i0 + r0 + i) * N + j0 + c0] = o;
    }
}

// ---------------------------------------------------------------------------
// Fused sigmoid-attention, FFMA2 + broadcast warp layout.
// lanes = n rows (l, l+32); warps = m / chunk columns.
// n-tile 64, m-tile 128, K channel-halved (Ks = 128 rows x 128 ch).
// ---------------------------------------------------------------------------

#define STAGE_K(m0_, h_) do {                                                  \
    _Pragma("unroll")                                                          \
    for (int s_ = 0; s_ < 16; s_++) {                                          \
        int lin_ = t + 256 * s_;                                               \
        int row_ = lin_ >> 5, ck_ = lin_ & 31;                                 \
        float4 v_ = *(const float4*)(p1b + (size_t)((m0_) + row_) * CCH +      \
                                     (h_) * 128 + ck_ * 4);                    \
        *(float4*)(Ks + row_ * 128 + (((ck_) ^ (row_ & 15)) << 2)) = v_;       \
    }                                                                          \
} while (0)

#define GEMM2_PASS(H_) do {                                                    \
    _Pragma("unroll 2")                                                        \
    for (int m_ = 0; m_ < 128; m_++) {                                         \
        ull pa_ = pack2(SsA[m_]);                                              \
        ull pb_ = pack2(SsB[m_]);                                              \
        _Pragma("unroll")                                                      \
        for (int q_ = 0; q_ < 4; q_++) {                                       \
            ulonglong2 kv_ = *(const ulonglong2*)(Ks + m_ * 128 +              \
                                (((w * 4 + q_) ^ (m_ & 15)) << 2));            \
            ffma2(ObA[H_][q_].x, pa_, kv_.x);                                  \
            ffma2(ObA[H_][q_].y, pa_, kv_.y);                                  \
            ffma2(ObB[H_][q_].x, pb_, kv_.x);                                  \
            ffma2(ObB[H_][q_].y, pb_, kv_.y);                                  \
        }                                                                      \
    }                                                                          \
} while (0)

__global__ __launch_bounds__(256, 1) void fused_kernel(
    const float* __restrict__ p1,
    const float* __restrict__ att2, const float* __restrict__ att3,
    const float* __restrict__ pa1, const float* __restrict__ pa2,
    const float* __restrict__ pa3, float* __restrict__ out)
{
    extern __shared__ float sm[];
    float* Qs = sm;                   // 64 x 256 ch (64 chunks), swizzled
    float* Ks = Qs + 64 * 256;        // 128 x 128 ch (32 chunks), swizzled
    float* Ss = Ks + 128 * 128;       // 64 x 133
    float* A2 = Ss + 64 * 133;        // 17 x 257 (padded)
    float* A3 = A2 + 17 * 257;        // 5 x 65  (padded)

    const int b  = blockIdx.y;
    const int n0 = blockIdx.x * 64;
    const int t  = threadIdx.x;
    const int w  = t >> 5, l = t & 31;
    const int sq = l & 15;            // swizzle key for both rows l, l+32

    const float* p1b = p1 + (size_t)b * N1D * CCH;
    const float sa1 = *pa1, sa2 = *pa2, sa3 = *pa3;
    const int r2lo = n0 >> 2;
    const int r3lo = n0 >> 4;

    // ---- stage Q tile (64 x 256), swizzled ----
#pragma unroll
    for (int i = 0; i < 16; i++) {
        int lin = t + 256 * i;
        int row = lin >> 6, ck = lin & 63;
        float4 v = *(const float4*)(p1b + (size_t)(n0 + row) * CCH + ck * 4);
        *(float4*)(Qs + row * 256 + ((ck ^ (row & 15)) << 2)) = v;
    }
    // ---- stage att2 window 17x256 (stride 257) ----
    for (int lin = t; lin < 17 * 256; lin += 256) {
        int rr = lin >> 8, cc = lin & 255;
        int src_r = min(r2lo + rr, 255);
        A2[rr * 257 + cc] = att2[((size_t)b * 256 + src_r) * 256 + cc];
    }
    // ---- stage att3 window 5x64 (stride 65) ----
    for (int lin = t; lin < 5 * 64; lin += 256) {
        int rr = lin >> 6, cc = lin & 63;
        int src_r = min(r3lo + rr, 63);
        A3[rr * 65 + cc] = att3[((size_t)b * 64 + src_r) * 64 + cc];
    }

    // per-row constants (rows na = n0+l, nb = na+32); fn/fn3 identical for both
    const int   na  = n0 + l;
    const int   rna = na >> 2;
    const float fn  = (float)(na & 3) * 0.25f;
    const float fn3 = (float)(na & 15) * 0.0625f;
    const float* Ar0a = A2 + (rna - r2lo) * 257;
    const float* Ar1a = A2 + (min(rna + 1, 255) - r2lo) * 257;
    const float* Ar0b = A2 + (rna + 8 - r2lo) * 257;
    const float* Ar1b = A2 + (min(rna + 9, 255) - r2lo) * 257;
    const int   rn3  = na >> 4;
    const float* Br0a = A3 + (rn3 - r3lo) * 65;
    const float* Br1a = A3 + (min(rn3 + 1, 63) - r3lo) * 65;
    const float* Br0b = A3 + (rn3 + 2 - r3lo) * 65;
    const float* Br1b = A3 + (min(rn3 + 3, 63) - r3lo) * 65;
    float* SsA = Ss + l * 133;
    float* SsB = Ss + (l + 32) * 133;

    ulonglong2 ObA[2][4], ObB[2][4];
#pragma unroll
    for (int h = 0; h < 2; h++)
#pragma unroll
        for (int q = 0; q < 4; q++) {
            ObA[h][q].x = 0ULL; ObA[h][q].y = 0ULL;
            ObB[h][q].x = 0ULL; ObB[h][q].y = 0ULL;
        }

    for (int mt = 0; mt < 8; mt++) {
        const int m0 = mt * 128;
        ull accA[16], accB[16];
#pragma unroll
        for (int j = 0; j < 16; j++) { accA[j] = 0ULL; accB[j] = 0ULL; }

        // ---- GEMM1: S = Q . K^T, two channel halves ----
#pragma unroll 1
        for (int h = 0; h < 2; h++) {
            __syncthreads();           // prior readers of Ks done
            STAGE_K(m0, h);
            __syncthreads();
#pragma unroll 2
            for (int ck = 0; ck < 32; ck++) {
                const int cq = h * 32 + ck;
                ulonglong2 qa = *(const ulonglong2*)(Qs + l * 256 + ((cq ^ sq) << 2));
                ulonglong2 qb = *(const ulonglong2*)(Qs + (l + 32) * 256 + ((cq ^ sq) << 2));
#pragma unroll
                for (int j = 0; j < 16; j++) {
                    ulonglong2 kv = *(const ulonglong2*)(Ks + (w * 16 + j) * 128 +
                                                         ((ck ^ j) << 2));
                    ffma2(accA[j], qa.x, kv.x);
                    ffma2(accA[j], qa.y, kv.y);
                    ffma2(accB[j], qb.x, kv.x);
                    ffma2(accB[j], qb.y, kv.y);
                }
            }
        }

        // ---- epilogue: gating lerp + sigmoid -> Ss ----
#pragma unroll
        for (int j = 0; j < 16; j++) {
            const int m  = m0 + w * 16 + j;
            const int rm = m >> 2;
            const float fm = (float)(m & 3) * 0.25f;
            const int c21 = min(rm + 1, 255);
            const int rm3 = m >> 4;
            const float fm3 = (float)(m & 15) * 0.0625f;
            const int c31 = min(rm3 + 1, 63);

            float h00 = (1.f - fm) * Ar0a[rm] + fm * Ar0a[c21];
            float h01 = (1.f - fm) * Ar1a[rm] + fm * Ar1a[c21];
            float h10 = (1.f - fm) * Ar0b[rm] + fm * Ar0b[c21];
            float h11 = (1.f - fm) * Ar1b[rm] + fm * Ar1b[c21];
            float v2a = (1.f - fn) * h00 + fn * h01;
            float v2b = (1.f - fn) * h10 + fn * h11;

            float g00 = (1.f - fm3) * Br0a[rm3] + fm3 * Br0a[c31];
            float g01 = (1.f - fm3) * Br1a[rm3] + fm3 * Br1a[c31];
            float g10 = (1.f - fm3) * Br0b[rm3] + fm3 * Br0b[c31];
            float g11 = (1.f - fm3) * Br1b[rm3] + fm3 * Br1b[c31];
            float v3a = (1.f - fn3) * g00 + fn3 * g01;
            float v3b = (1.f - fn3) * g10 + fn3 * g11;

            float2 fa = unpack2(accA[j]);
            float2 fb = unpack2(accB[j]);
            float va = sa1 * (fa.x + fa.y) + sa2 * v2a + sa3 * v3a;
            float vb = sa1 * (fb.x + fb.y) + sa2 * v2b + sa3 * v3b;
            SsA[w * 16 + j] = 1.0f / (1.0f + __expf(-va));
            SsB[w * 16 + j] = 1.0f / (1.0f + __expf(-vb));
        }
        __syncthreads();               // Ss visible; Ks still holds half 1

        // ---- GEMM2 half 1 (chunks 32..63) ----
        GEMM2_PASS(1);
        __syncthreads();
        STAGE_K(m0, 0);                // restage half 0
        __syncthreads();
        // ---- GEMM2 half 0 (chunks 0..31) ----
        GEMM2_PASS(0);
    }

    // ---- final: out = O + p1 (p1 resident in Qs) ----
    float* orowA = out + ((size_t)(b * N1D + n0 + l)) * CCH;
    float* orowB = out + ((size_t)(b * N1D + n0 + l + 32)) * CCH;
#pragma unroll
    for (int h = 0; h < 2; h++)
#pragma unroll
        for (int q = 0; q < 4; q++) {
            const int c = h * 32 + w * 4 + q;
            float4 pva = *(const float4*)(Qs + l * 256 + ((c ^ sq) << 2));
            float4 pvb = *(const float4*)(Qs + (l + 32) * 256 + ((c ^ sq) << 2));
            float2 la = unpack2(ObA[h][q].x), ha = unpack2(ObA[h][q].y);
            float2 lb = unpack2(ObB[h][q].x), hb = unpack2(ObB[h][q].y);
            float4 oa = make_float4(la.x + pva.x, la.y + pva.y,
                                    ha.x + pva.z, ha.y + pva.w);
            float4 ob = make_float4(lb.x + pvb.x, lb.y + pvb.y,
                                    hb.x + pvb.z, hb.y + pvb.w);
            *(float4*)(orowA + c * 4) = oa;
            *(float4*)(orowB + c * 4) = ob;
        }
}

// ---------------------------------------------------------------------------
extern "C" void kernel_launch(void* const* d_in, const int* in_sizes, int n_in,
                              void* d_out, int out_size)
{
    const float* f1 = (const float*)d_in[0];
    const float* f2 = (const float*)d_in[1];
    const float* f3 = (const float*)d_in[2];
    const float* w1 = (const float*)d_in[3];
    const float* b1 = (const float*)d_in[4];
    const float* w2 = (const float*)d_in[5];
    const float* b2 = (const float*)d_in[6];
    const float* w3 = (const float*)d_in[7];
    const float* b3 = (const float*)d_in[8];
    const float* a1 = (const float*)d_in[9];
    const float* a2 = (const float*)d_in[10];
    const float* a3 = (const float*)d_in[11];
    float* out = (float*)d_out;

    float *p1, *x2, *x3, *att2, *att3;
    cudaGetSymbolAddress((void**)&p1,   g_p1);
    cudaGetSymbolAddress((void**)&x2,   g_x2);
    cudaGetSymbolAddress((void**)&x3,   g_x3);
    cudaGetSymbolAddress((void**)&att2, g_att2);
    cudaGetSymbolAddress((void**)&att3, g_att3);

    // bias pre-init for K-split projections
    init_bias_kernel<<<(BATCH * 256 * CCH) / 1024, 256>>>(x2, b2);
    init_bias_kernel<<<(BATCH * 64  * CCH) / 1024, 256>>>(x3, b3);

    // 1x1 conv projections
    proj_kernel<<<dim3((BATCH * N1D) / 64, 1), 256>>>(f1, w1, b1, p1, 256);
    proj_kernel<<<dim3((BATCH * 256) / 64, 2), 256>>>(f2, w2, b2, x2, 512);
    proj_kernel<<<dim3((BATCH * 64)  / 64, 4), 256>>>(f3, w3, b3, x3, 1024);

    // small Gram matrices
    gram128_kernel<<<dim3(2, 2, BATCH), 256>>>(x2, att2, 256);
    attnt_kernel<<<dim3(1, 1, BATCH), 256>>>(x3, att3, 64);

    // fused sigmoid-attention + output
    const int smem_bytes = (64 * 256 + 128 * 128 + 64 * 133 + 17 * 257 + 5 * 65) * 4;
    cudaFuncSetAttribute(fused_kernel,
                         cudaFuncAttributeMaxDynamicSharedMemorySize, smem_bytes);
    fused_kernel<<<dim3(16, BATCH), 256, smem_bytes>>>(p1, att2, att3,
                                                       a1, a2, a3, out);
}

// round 6
// speedup vs baseline: 1.8948x; 1.8947x over previous
#include <cuda_runtime.h>
#include <cuda_bf16.h>
#include <math.h>
#include <stdint.h>

#define BATCH 16
#define N1D 1024
#define CCH 256

// ---------------- device scratch ----------------
__device__ float g_p1[BATCH * N1D * CCH];
__device__ float g_x2[BATCH * 256 * CCH];
__device__ float g_x3[BATCH * 64 * CCH];
__device__ float g_att2[BATCH * 256 * 256];
__device__ float g_att3[BATCH * 64 * 64];
__device__ __nv_bfloat16 g_x1h[BATCH * N1D * CCH];
__device__ __nv_bfloat16 g_x1l[BATCH * N1D * CCH];

// ---------------- warp-MMA helpers (baseline PTX, sm_80+) ----------------
__device__ __forceinline__ uint32_t smem_u32(const void* p) {
    uint32_t a;
    asm("{ .reg .u64 t; cvta.to.shared.u64 t, %1; cvt.u32.u64 %0, t; }"
        : "=r"(a) : "l"(p));
    return a;
}
__device__ __forceinline__ void ldsm4(uint32_t* r, uint32_t a) {
    asm volatile("ldmatrix.sync.aligned.m8n8.x4.shared.b16 {%0,%1,%2,%3}, [%4];"
        : "=r"(r[0]), "=r"(r[1]), "=r"(r[2]), "=r"(r[3]) : "r"(a));
}
__device__ __forceinline__ void ldsm4t(uint32_t* r, uint32_t a) {
    asm volatile("ldmatrix.sync.aligned.m8n8.x4.trans.shared.b16 {%0,%1,%2,%3}, [%4];"
        : "=r"(r[0]), "=r"(r[1]), "=r"(r[2]), "=r"(r[3]) : "r"(a));
}
__device__ __forceinline__ void mma_bf16(float* d, const uint32_t* a,
                                         const uint32_t* b) {
    asm volatile(
        "mma.sync.aligned.m16n8k16.row.col.f32.bf16.bf16.f32 "
        "{%0,%1,%2,%3}, {%4,%5,%6,%7}, {%8,%9}, {%0,%1,%2,%3};"
        : "+f"(d[0]), "+f"(d[1]), "+f"(d[2]), "+f"(d[3])
        : "r"(a[0]), "r"(a[1]), "r"(a[2]), "r"(a[3]), "r"(b[0]), "r"(b[1]));
}
__device__ __forceinline__ unsigned pack_bf16(__nv_bfloat16 a, __nv_bfloat16 b) {
    return ((unsigned)__bfloat16_as_ushort(b) << 16) | (unsigned)__bfloat16_as_ushort(a);
}

// ---------------------------------------------------------------------------
__global__ void init_bias_kernel(float* __restrict__ out,
                                 const float* __restrict__ bias)
{
    int idx = blockIdx.x * 256 + threadIdx.x;
    int cj = idx & 63;
    float4 bv = *(const float4*)&bias[cj * 4];
    *(float4*)&out[idx * 4] = bv;
}

// ---------------------------------------------------------------------------
// Projection (fp32)
// ---------------------------------------------------------------------------
__global__ __launch_bounds__(256) void proj_kernel(
    const float* __restrict__ A, const float* __restrict__ W,
    const float* __restrict__ bias, float* __restrict__ out, int KDIM)
{
    __shared__ float As[32 * 68];
    __shared__ float Ws[32 * 256];
    const int t  = threadIdx.x;
    const int ty = t >> 4, tx = t & 15;
    const int r0 = ty * 4;
    const int row0 = blockIdx.x * 64;
    const int kd    = KDIM / gridDim.y;
    const int kbase = blockIdx.y * kd;

    float4 acc[4][4];
#pragma unroll
    for (int i = 0; i < 4; i++)
#pragma unroll
        for (int q = 0; q < 4; q++) acc[i][q] = make_float4(0.f, 0.f, 0.f, 0.f);

    for (int k0 = 0; k0 < kd; k0 += 32) {
        const int kb = kbase + k0;
#pragma unroll
        for (int s = 0; s < 2; s++) {
            int lin = t + 256 * s;
            int row = lin >> 3, kc = lin & 7;
            float4 v = *(const float4*)&A[(size_t)(row0 + row) * KDIM + kb + kc * 4];
            As[(kc * 4 + 0) * 68 + row] = v.x;
            As[(kc * 4 + 1) * 68 + row] = v.y;
            As[(kc * 4 + 2) * 68 + row] = v.z;
            As[(kc * 4 + 3) * 68 + row] = v.w;
        }
#pragma unroll
        for (int s = 0; s < 8; s++) {
            int lin = t + 256 * s;
            int k = lin >> 6, ck = lin & 63;
            *(float4*)&Ws[k * 256 + ck * 4] =
                *(const float4*)&W[(size_t)(kb + k) * CCH + ck * 4];
        }
        __syncthreads();
#pragma unroll
        for (int k = 0; k < 32; k++) {
            float4 a4 = *(const float4*)&As[k * 68 + r0];
#pragma unroll
            for (int q = 0; q < 4; q++) {
                float4 w4 = *(const float4*)&Ws[k * 256 + (tx + 16 * q) * 4];
                acc[0][q].x += a4.x * w4.x; acc[0][q].y += a4.x * w4.y;
                acc[0][q].z += a4.x * w4.z; acc[0][q].w += a4.x * w4.w;
                acc[1][q].x += a4.y * w4.x; acc[1][q].y += a4.y * w4.y;
                acc[1][q].z += a4.y * w4.z; acc[1][q].w += a4.y * w4.w;
                acc[2][q].x += a4.z * w4.x; acc[2][q].y += a4.z * w4.y;
                acc[2][q].z += a4.z * w4.z; acc[2][q].w += a4.z * w4.w;
                acc[3][q].x += a4.w * w4.x; acc[3][q].y += a4.w * w4.y;
                acc[3][q].z += a4.w * w4.z; acc[3][q].w += a4.w * w4.w;
            }
        }
        __syncthreads();
    }

    if (gridDim.y == 1) {
#pragma unroll
        for (int q = 0; q < 4; q++) {
            float4 bv = *(const float4*)&bias[(tx + 16 * q) * 4];
#pragma unroll
            for (int i = 0; i < 4; i++) {
                float4 o = make_float4(acc[i][q].x + bv.x, acc[i][q].y + bv.y,
                                       acc[i][q].z + bv.z, acc[i][q].w + bv.w);
                *(float4*)&out[(size_t)(row0 + r0 + i) * CCH + (tx + 16 * q) * 4] = o;
            }
        }
    } else {
#pragma unroll
        for (int q = 0; q < 4; q++)
#pragma unroll
            for (int i = 0; i < 4; i++) {
                float* dst = &out[(size_t)(row0 + r0 + i) * CCH + (tx + 16 * q) * 4];
                atomicAdd(dst + 0, acc[i][q].x);
                atomicAdd(dst + 1, acc[i][q].y);
                atomicAdd(dst + 2, acc[i][q].z);
                atomicAdd(dst + 3, acc[i][q].w);
            }
    }
}

// ---------------------------------------------------------------------------
// Gram kernels (fp32)
// ---------------------------------------------------------------------------
__global__ __launch_bounds__(256) void gram128_kernel(
    const float* __restrict__ X, float* __restrict__ out, int N)
{
    __shared__ float At[16 * 132];
    __shared__ float Bt[16 * 132];
    const int b  = blockIdx.z;
    const int i0 = blockIdx.x * 128, j0 = blockIdx.y * 128;
    const int t  = threadIdx.x;
    const int ty = t >> 4, tx = t & 15;
    const int ra = ty * 4, ca = tx * 4;
    const float* Xb = X + (size_t)b * N * CCH;

    float acc[8][8];
#pragma unroll
    for (int i = 0; i < 8; i++)
#pragma unroll
        for (int j = 0; j < 8; j++) acc[i][j] = 0.f;

    for (int k0 = 0; k0 < CCH; k0 += 16) {
#pragma unroll
        for (int s = 0; s < 2; s++) {
            int lin = t + 256 * s;
            int row = lin >> 2, kc = lin & 3;
            float4 va = *(const float4*)&Xb[(size_t)(i0 + row) * CCH + k0 + kc * 4];
            At[(kc * 4 + 0) * 132 + row] = va.x;
            At[(kc * 4 + 1) * 132 + row] = va.y;
            At[(kc * 4 + 2) * 132 + row] = va.z;
            At[(kc * 4 + 3) * 132 + row] = va.w;
            float4 vb = *(const float4*)&Xb[(size_t)(j0 + row) * CCH + k0 + kc * 4];
            Bt[(kc * 4 + 0) * 132 + row] = vb.x;
            Bt[(kc * 4 + 1) * 132 + row] = vb.y;
            Bt[(kc * 4 + 2) * 132 + row] = vb.z;
            Bt[(kc * 4 + 3) * 132 + row] = vb.w;
        }
        __syncthreads();
#pragma unroll
        for (int k = 0; k < 16; k++) {
            float4 a0 = *(const float4*)&At[k * 132 + ra];
            float4 a1 = *(const float4*)&At[k * 132 + 64 + ra];
            float4 b0 = *(const float4*)&Bt[k * 132 + ca];
            float4 b1 = *(const float4*)&Bt[k * 132 + 64 + ca];
            float av[8] = {a0.x, a0.y, a0.z, a0.w, a1.x, a1.y, a1.z, a1.w};
            float bv[8] = {b0.x, b0.y, b0.z, b0.w, b1.x, b1.y, b1.z, b1.w};
#pragma unroll
            for (int i = 0; i < 8; i++)
#pragma unroll
                for (int j = 0; j < 8; j++)
                    acc[i][j] += av[i] * bv[j];
        }
        __syncthreads();
    }

#pragma unroll
    for (int hr = 0; hr < 2; hr++)
#pragma unroll
        for (int i = 0; i < 4; i++) {
            int row = i0 + hr * 64 + ra + i;
            float4 o0 = make_float4(acc[hr*4+i][0], acc[hr*4+i][1],
                                    acc[hr*4+i][2], acc[hr*4+i][3]);
            float4 o1 = make_float4(acc[hr*4+i][4], acc[hr*4+i][5],
                                    acc[hr*4+i][6], acc[hr*4+i][7]);
            *(float4*)&out[(size_t)b * N * N + (size_t)row * N + j0 + ca]      = o0;
            *(float4*)&out[(size_t)b * N * N + (size_t)row * N + j0 + 64 + ca] = o1;
        }
}

__global__ __launch_bounds__(256) void attnt_kernel(
    const float* __restrict__ X, float* __restrict__ out, int N)
{
    __shared__ float Ai[32][65];
    __shared__ float Bj[32][65];
    const int b  = blockIdx.z;
    const int i0 = blockIdx.x * 64, j0 = blockIdx.y * 64;
    const int t  = threadIdx.x;
    const int ty = t >> 4, tx = t & 15;
    const int r0 = ty * 4, c0 = tx * 4;
    const float* Xb = X + (size_t)b * N * CCH;

    float acc[4][4] = {};
    for (int k0 = 0; k0 < CCH; k0 += 32) {
#pragma unroll
        for (int i = 0; i < 8; i++) {
            int lin = t + 256 * i;
            int r = lin >> 5, k = lin & 31;
            Ai[k][r] = Xb[(size_t)(i0 + r) * CCH + k0 + k];
            Bj[k][r] = Xb[(size_t)(j0 + r) * CCH + k0 + k];
        }
        __syncthreads();
#pragma unroll
        for (int k = 0; k < 32; k++) {
            float a[4], bb[4];
#pragma unroll
            for (int i = 0; i < 4; i++) a[i]  = Ai[k][r0 + i];
#pragma unroll
            for (int j = 0; j < 4; j++) bb[j] = Bj[k][c0 + j];
#pragma unroll
            for (int i = 0; i < 4; i++)
#pragma unroll
                for (int j = 0; j < 4; j++)
                    acc[i][j] += a[i] * bb[j];
        }
        __syncthreads();
    }
#pragma unroll
    for (int i = 0; i < 4; i++) {
        float4 o = make_float4(acc[i][0], acc[i][1], acc[i][2], acc[i][3]);
        *(float4*)&out[(size_t)b * N * N + (size_t)(i0 + r0 + i) * N + j0 + c0] = o;
    }
}

// ---------------------------------------------------------------------------
// split: p1 fp32 -> x1 hi/lo bf16 (row-major)
// ---------------------------------------------------------------------------
__global__ __launch_bounds__(256) void split_kernel(
    const float* __restrict__ p1,
    __nv_bfloat16* __restrict__ xh, __nv_bfloat16* __restrict__ xl)
{
    size_t i4 = (size_t)blockIdx.x * 256 + threadIdx.x;
    float4 v = *(const float4*)(p1 + i4 * 4);
    float f[4] = {v.x, v.y, v.z, v.w};
    __nv_bfloat16 h[4], lo[4];
#pragma unroll
    for (int i = 0; i < 4; i++) {
        h[i]  = __float2bfloat16_rn(f[i]);
        lo[i] = __float2bfloat16_rn(f[i] - __bfloat162float(h[i]));
    }
    uint2 uh = make_uint2(pack_bf16(h[0], h[1]), pack_bf16(h[2], h[3]));
    uint2 ul = make_uint2(pack_bf16(lo[0], lo[1]), pack_bf16(lo[2], lo[3]));
    *(uint2*)(xh + i4 * 4) = uh;
    *(uint2*)(xl + i4 * 4) = ul;
}

// ---------------------------------------------------------------------------
// Fused sigmoid-attention via warp MMA (bf16 split).
// CTA: 256 thr = 8 warps, n-tile 64, m-tile 128, K in 128-ch halves.
// Warp grid: wn = w&1 (32 rows), wq = w>>1 (32 m-cols / 32-ch window).
// ---------------------------------------------------------------------------
#define QSTR 264
#define KSTR 136

#define GEMM2_HALF(OARR) do {                                                  \
    _Pragma("unroll")                                                          \
    for (int kc_ = 0; kc_ < 8; kc_++) {                                        \
        uint32_t a2h[2][4], a2l[2][4];                                         \
        _Pragma("unroll")                                                      \
        for (int mf_ = 0; mf_ < 2; mf_++) {                                    \
            uint32_t off_ = ((wn * 32 + mf_ * 16 + aRow) * KSTR +              \
                             kc_ * 16 + aCol) * 2;                             \
            ldsm4(a2h[mf_], sh0 + off_);                                       \
            ldsm4(a2l[mf_], sl0 + off_);                                       \
        }                                                                      \
        uint32_t b2h[4][2], b2l[4][2];                                         \
        _Pragma("unroll")                                                      \
        for (int bt_ = 0; bt_ < 2; bt_++) {                                    \
            uint32_t off_ = ((kc_ * 16 + aRow) * KSTR +                        \
                             wq * 32 + bt_ * 16 + aCol) * 2;                   \
            uint32_t r4_[4];                                                   \
            ldsm4t(r4_, kh0 + off_);                                           \
            b2h[bt_*2][0]=r4_[0]; b2h[bt_*2][1]=r4_[1];                        \
            b2h[bt_*2+1][0]=r4_[2]; b2h[bt_*2+1][1]=r4_[3];                    \
            ldsm4t(r4_, kl0 + off_);                                           \
            b2l[bt_*2][0]=r4_[0]; b2l[bt_*2][1]=r4_[1];                        \
            b2l[bt_*2+1][0]=r4_[2]; b2l[bt_*2+1][1]=r4_[3];                    \
        }                                                                      \
        _Pragma("unroll")                                                      \
        for (int mf_ = 0; mf_ < 2; mf_++)                                      \
        _Pragma("unroll")                                                      \
        for (int f_ = 0; f_ < 4; f_++) {                                       \
            mma_bf16(OARR[mf_][f_], a2h[mf_], b2h[f_]);                        \
            mma_bf16(OARR[mf_][f_], a2h[mf_], b2l[f_]);                        \
            mma_bf16(OARR[mf_][f_], a2l[mf_], b2h[f_]);                        \
        }                                                                      \
    }                                                                          \
} while (0)

__global__ __launch_bounds__(256, 1) void fused_mma_kernel(
    const __nv_bfloat16* __restrict__ xh, const __nv_bfloat16* __restrict__ xl,
    const float* __restrict__ p1,
    const float* __restrict__ att2, const float* __restrict__ att3,
    const float* __restrict__ pa1, const float* __restrict__ pa2,
    const float* __restrict__ pa3, float* __restrict__ out)
{
    extern __shared__ char smbuf[];
    __nv_bfloat16* Qh = (__nv_bfloat16*)smbuf;       // 64 x 264
    __nv_bfloat16* Ql = Qh + 64 * QSTR;
    __nv_bfloat16* Kh = Ql + 64 * QSTR;              // 128 x 136
    __nv_bfloat16* Kl = Kh + 128 * KSTR;
    __nv_bfloat16* Sh = Kl + 128 * KSTR;             // 64 x 136
    __nv_bfloat16* Sl = Sh + 64 * KSTR;
    float* A2s = (float*)(Sl + 64 * KSTR);           // 17 x 257
    float* A3s = A2s + 17 * 257;                     // 5 x 65

    const int b  = blockIdx.y;
    const int n0 = blockIdx.x * 64;
    const int t  = threadIdx.x, w = t >> 5, l = t & 31;
    const int wn = w & 1, wq = w >> 1;
    const int aRow = l & 15, aCol = (l >> 4) * 8;           // A / trans-B lanes
    const int bRow = ((l >> 4) * 8) + (l & 7);              // gemm1 B lanes
    const int bCol = ((l >> 3) & 1) * 8;

    const __nv_bfloat16* Xh = xh + (size_t)b * N1D * CCH;
    const __nv_bfloat16* Xl = xl + (size_t)b * N1D * CCH;
    const float sa1 = *pa1, sa2 = *pa2, sa3 = *pa3;
    const int r2lo = n0 >> 2, r3lo = n0 >> 4;

    // ---- stage Q hi/lo (64 x 256) ----
#pragma unroll
    for (int i = 0; i < 8; i++) {
        int idx = t + 256 * i;                 // 2048 uint4 per tensor
        int r = idx >> 5, c = idx & 31;
        *(uint4*)(Qh + r * QSTR + c * 8) =
            *(const uint4*)(Xh + (size_t)(n0 + r) * CCH + c * 8);
        *(uint4*)(Ql + r * QSTR + c * 8) =
            *(const uint4*)(Xl + (size_t)(n0 + r) * CCH + c * 8);
    }
    // ---- stage att2 window (17 x 256, stride 257) / att3 (5 x 64, stride 65) ----
    for (int i = t; i < 17 * 256; i += 256) {
        int rr = i >> 8, cc = i & 255;
        A2s[rr * 257 + cc] = att2[((size_t)b * 256 + min(r2lo + rr, 255)) * 256 + cc];
    }
    for (int i = t; i < 5 * 64; i += 256) {
        int rr = i >> 6, cc = i & 63;
        A3s[rr * 65 + cc] = att3[((size_t)b * 64 + min(r3lo + rr, 63)) * 64 + cc];
    }

    const uint32_t qh0 = smem_u32(Qh), ql0 = smem_u32(Ql);
    const uint32_t kh0 = smem_u32(Kh), kl0 = smem_u32(Kl);
    const uint32_t sh0 = smem_u32(Sh), sl0 = smem_u32(Sl);

    // per-thread row gating constants (4 rows: mf*2+pair)
    const float* R0p[4]; const float* R1p[4];
    const float* S0p[4]; const float* S1p[4];
    float fnv[4], fn3v[4];
#pragma unroll
    for (int rr = 0; rr < 4; rr++) {
        int n = n0 + wn * 32 + (rr >> 1) * 16 + (l >> 2) + (rr & 1) * 8;
        int rn = n >> 2;
        fnv[rr] = (float)(n & 3) * 0.25f;
        R0p[rr] = A2s + (rn - r2lo) * 257;
        R1p[rr] = A2s + (min(rn + 1, 255) - r2lo) * 257;
        int rn3 = n >> 4;
        fn3v[rr] = (float)(n & 15) * 0.0625f;
        S0p[rr] = A3s + (rn3 - r3lo) * 65;
        S1p[rr] = A3s + (min(rn3 + 1, 63) - r3lo) * 65;
    }

    float O0[2][4][4], O1[2][4][4];
#pragma unroll
    for (int mf = 0; mf < 2; mf++)
#pragma unroll
        for (int f = 0; f < 4; f++)
#pragma unroll
            for (int e = 0; e < 4; e++) { O0[mf][f][e] = 0.f; O1[mf][f][e] = 0.f; }

    for (int mt = 0; mt < 8; mt++) {
        const int m0 = mt * 128;
        float S[2][4][4];
#pragma unroll
        for (int mf = 0; mf < 2; mf++)
#pragma unroll
            for (int nf = 0; nf < 4; nf++)
#pragma unroll
                for (int e = 0; e < 4; e++) S[mf][nf][e] = 0.f;

        // ---- GEMM1: S = Q . K^T over 2 channel halves ----
#pragma unroll 1
        for (int h = 0; h < 2; h++) {
            __syncthreads();
#pragma unroll
            for (int i = 0; i < 8; i++) {      // stage K half: 128 rows x 128 ch
                int idx = t + 256 * i;
                int r = idx >> 4, c = idx & 15;
                *(uint4*)(Kh + r * KSTR + c * 8) =
                    *(const uint4*)(Xh + (size_t)(m0 + r) * CCH + h * 128 + c * 8);
                *(uint4*)(Kl + r * KSTR + c * 8) =
                    *(const uint4*)(Xl + (size_t)(m0 + r) * CCH + h * 128 + c * 8);
            }
            __syncthreads();
#pragma unroll
            for (int kc = 0; kc < 8; kc++) {
                uint32_t a1h[2][4], a1l[2][4];
#pragma unroll
                for (int mf = 0; mf < 2; mf++) {
                    uint32_t off = ((wn * 32 + mf * 16 + aRow) * QSTR +
                                    h * 128 + kc * 16 + aCol) * 2;
                    ldsm4(a1h[mf], qh0 + off);
                    ldsm4(a1l[mf], ql0 + off);
                }
                uint32_t b1h[4][2], b1l[4][2];
#pragma unroll
                for (int bt = 0; bt < 2; bt++) {
                    uint32_t off = ((wq * 32 + bt * 16 + bRow) * KSTR +
                                    kc * 16 + bCol) * 2;
                    uint32_t r4[4];
                    ldsm4(r4, kh0 + off);
                    b1h[bt*2][0]=r4[0]; b1h[bt*2][1]=r4[1];
                    b1h[bt*2+1][0]=r4[2]; b1h[bt*2+1][1]=r4[3];
                    ldsm4(r4, kl0 + off);
                    b1l[bt*2][0]=r4[0]; b1l[bt*2][1]=r4[1];
                    b1l[bt*2+1][0]=r4[2]; b1l[bt*2+1][1]=r4[3];
                }
#pragma unroll
                for (int mf = 0; mf < 2; mf++)
#pragma unroll
                for (int nf = 0; nf < 4; nf++) {
                    mma_bf16(S[mf][nf], a1h[mf], b1h[nf]);
                    mma_bf16(S[mf][nf], a1h[mf], b1l[nf]);
                    mma_bf16(S[mf][nf], a1l[mf], b1h[nf]);
                }
            }
        }

        // ---- epilogue: gating + sigmoid -> Sh/Sl ----
#pragma unroll
        for (int mf = 0; mf < 2; mf++)
#pragma unroll
        for (int nf = 0; nf < 4; nf++)
#pragma unroll
        for (int pr = 0; pr < 2; pr++) {
            const int rr = mf * 2 + pr;
            const int row_l = wn * 32 + mf * 16 + (l >> 2) + pr * 8;
            const int col_l = wq * 32 + nf * 8 + (l & 3) * 2;
            const float fn = fnv[rr], fn3 = fn3v[rr];
            const float *R0 = R0p[rr], *R1 = R1p[rr];
            const float *T0 = S0p[rr], *T1 = S1p[rr];
            __nv_bfloat16 hh[2], hl[2];
#pragma unroll
            for (int e = 0; e < 2; e++) {
                int m = m0 + col_l + e;
                float Sv = S[mf][nf][pr * 2 + e];
                int cm = m >> 2;
                float fm = (float)(m & 3) * 0.25f;
                int cm1 = min(cm + 1, 255);
                float v2 = (1.f - fn) * ((1.f - fm) * R0[cm] + fm * R0[cm1]) +
                           fn         * ((1.f - fm) * R1[cm] + fm * R1[cm1]);
                int cm3 = m >> 4;
                float fm3 = (float)(m & 15) * 0.0625f;
                int cm31 = min(cm3 + 1, 63);
                float v3 = (1.f - fn3) * ((1.f - fm3) * T0[cm3] + fm3 * T0[cm31]) +
                           fn3         * ((1.f - fm3) * T1[cm3] + fm3 * T1[cm31]);
                float val = sa1 * Sv + sa2 * v2 + sa3 * v3;
                float sg = 1.0f / (1.0f + __expf(-val));
                hh[e] = __float2bfloat16_rn(sg);
                hl[e] = __float2bfloat16_rn(sg - __bfloat162float(hh[e]));
            }
            *(uint32_t*)&Sh[row_l * KSTR + col_l] = pack_bf16(hh[0], hh[1]);
            *(uint32_t*)&Sl[row_l * KSTR + col_l] = pack_bf16(hl[0], hl[1]);
        }
        __syncthreads();

        // ---- GEMM2 half 1 (Ks holds ch 128..255) ----
        GEMM2_HALF(O1);
        __syncthreads();
#pragma unroll
        for (int i = 0; i < 8; i++) {          // restage K half 0
            int idx = t + 256 * i;
            int r = idx >> 4, c = idx & 15;
            *(uint4*)(Kh + r * KSTR + c * 8) =
                *(const uint4*)(Xh + (size_t)(m0 + r) * CCH + c * 8);
            *(uint4*)(Kl + r * KSTR + c * 8) =
                *(const uint4*)(Xl + (size_t)(m0 + r) * CCH + c * 8);
        }
        __syncthreads();
        // ---- GEMM2 half 0 (ch 0..127) ----
        GEMM2_HALF(O0);
    }

    // ---- final: out = O + p1 ----
#pragma unroll
    for (int mf = 0; mf < 2; mf++)
#pragma unroll
    for (int f = 0; f < 4; f++)
#pragma unroll
    for (int pr = 0; pr < 2; pr++) {
        const int n = n0 + wn * 32 + mf * 16 + (l >> 2) + pr * 8;
        const int ch0 = wq * 32 + f * 8 + (l & 3) * 2;
        {
            const size_t o = ((size_t)(b * N1D + n)) * CCH + ch0;
            float2 pv = *(const float2*)(p1 + o);
            float2 ov = make_float2(O0[mf][f][pr*2+0] + pv.x,
                                    O0[mf][f][pr*2+1] + pv.y);
            *(float2*)(out + o) = ov;
        }
        {
            const size_t o = ((size_t)(b * N1D + n)) * CCH + 128 + ch0;
            float2 pv = *(const float2*)(p1 + o);
            float2 ov = make_float2(O1[mf][f][pr*2+0] + pv.x,
                                    O1[mf][f][pr*2+1] + pv.y);
            *(float2*)(out + o) = ov;
        }
    }
}

// ---------------------------------------------------------------------------
extern "C" void kernel_launch(void* const* d_in, const int* in_sizes, int n_in,
                              void* d_out, int out_size)
{
    const float* f1 = (const float*)d_in[0];
    const float* f2 = (const float*)d_in[1];
    const float* f3 = (const float*)d_in[2];
    const float* w1 = (const float*)d_in[3];
    const float* b1 = (const float*)d_in[4];
    const float* w2 = (const float*)d_in[5];
    const float* b2 = (const float*)d_in[6];
    const float* w3 = (const float*)d_in[7];
    const float* b3 = (const float*)d_in[8];
    const float* a1 = (const float*)d_in[9];
    const float* a2 = (const float*)d_in[10];
    const float* a3 = (const float*)d_in[11];
    float* out = (float*)d_out;

    float *p1, *x2, *x3, *att2, *att3;
    __nv_bfloat16 *x1h, *x1l;
    cudaGetSymbolAddress((void**)&p1,   g_p1);
    cudaGetSymbolAddress((void**)&x2,   g_x2);
    cudaGetSymbolAddress((void**)&x3,   g_x3);
    cudaGetSymbolAddress((void**)&att2, g_att2);
    cudaGetSymbolAddress((void**)&att3, g_att3);
    cudaGetSymbolAddress((void**)&x1h,  g_x1h);
    cudaGetSymbolAddress((void**)&x1l,  g_x1l);

    init_bias_kernel<<<(BATCH * 256 * CCH) / 1024, 256>>>(x2, b2);
    init_bias_kernel<<<(BATCH * 64  * CCH) / 1024, 256>>>(x3, b3);

    proj_kernel<<<dim3((BATCH * N1D) / 64, 1), 256>>>(f1, w1, b1, p1, 256);
    proj_kernel<<<dim3((BATCH * 256) / 64, 2), 256>>>(f2, w2, b2, x2, 512);
    proj_kernel<<<dim3((BATCH * 64)  / 64, 4), 256>>>(f3, w3, b3, x3, 1024);

    gram128_kernel<<<dim3(2, 2, BATCH), 256>>>(x2, att2, 256);
    attnt_kernel<<<dim3(1, 1, BATCH), 256>>>(x3, att3, 64);

    split_kernel<<<(BATCH * N1D * CCH) / 1024, 256>>>(p1, x1h, x1l);

    const int smem_bytes =
        (64 * QSTR * 2 + 128 * KSTR * 2 + 64 * KSTR * 2) * 2  // bf16 tiles
        + (17 * 257 + 5 * 65) * 4;                            // fp32 gating
    cudaFuncSetAttribute(fused_mma_kernel,
                         cudaFuncAttributeMaxDynamicSharedMemorySize, smem_bytes);
    fused_mma_kernel<<<dim3(16, BATCH), 256, smem_bytes>>>(
        x1h, x1l, p1, att2, att3, a1, a2, a3, out);
}

// round 7
// speedup vs baseline: 2.1804x; 1.1507x over previous
#include <cuda_runtime.h>
#include <cuda_bf16.h>
#include <math.h>
#include <stdint.h>

#define BATCH 16
#define N1D 1024
#define CCH 256

// ---------------- device scratch ----------------
__device__ float g_p1[BATCH * N1D * CCH];
__device__ float g_x3[BATCH * 64 * CCH];
__device__ float g_att2[BATCH * 256 * 256];
__device__ float g_att3[BATCH * 64 * 64];
__device__ __nv_bfloat16 g_x1h[BATCH * N1D * CCH];
__device__ __nv_bfloat16 g_x1l[BATCH * N1D * CCH];
__device__ __nv_bfloat16 g_x2h[BATCH * 256 * CCH];
__device__ __nv_bfloat16 g_x2l[BATCH * 256 * CCH];
__device__ __nv_bfloat16 g_f1h[BATCH * N1D * CCH];
__device__ __nv_bfloat16 g_f1l[BATCH * N1D * CCH];
__device__ __nv_bfloat16 g_f2h[BATCH * 256 * 512];
__device__ __nv_bfloat16 g_f2l[BATCH * 256 * 512];
__device__ __nv_bfloat16 g_f3h[BATCH * 64 * 1024];
__device__ __nv_bfloat16 g_f3l[BATCH * 64 * 1024];
__device__ __nv_bfloat16 g_w1h[256 * 256],  g_w1l[256 * 256];
__device__ __nv_bfloat16 g_w2h[512 * 256],  g_w2l[512 * 256];
__device__ __nv_bfloat16 g_w3h[1024 * 256], g_w3l[1024 * 256];

// ---------------- warp-MMA helpers ----------------
__device__ __forceinline__ uint32_t smem_u32(const void* p) {
    uint32_t a;
    asm("{ .reg .u64 t; cvta.to.shared.u64 t, %1; cvt.u32.u64 %0, t; }"
        : "=r"(a) : "l"(p));
    return a;
}
__device__ __forceinline__ void ldsm4(uint32_t* r, uint32_t a) {
    asm volatile("ldmatrix.sync.aligned.m8n8.x4.shared.b16 {%0,%1,%2,%3}, [%4];"
        : "=r"(r[0]), "=r"(r[1]), "=r"(r[2]), "=r"(r[3]) : "r"(a));
}
__device__ __forceinline__ void ldsm4t(uint32_t* r, uint32_t a) {
    asm volatile("ldmatrix.sync.aligned.m8n8.x4.trans.shared.b16 {%0,%1,%2,%3}, [%4];"
        : "=r"(r[0]), "=r"(r[1]), "=r"(r[2]), "=r"(r[3]) : "r"(a));
}
__device__ __forceinline__ void mma_bf16(float* d, const uint32_t* a,
                                         const uint32_t* b) {
    asm volatile(
        "mma.sync.aligned.m16n8k16.row.col.f32.bf16.bf16.f32 "
        "{%0,%1,%2,%3}, {%4,%5,%6,%7}, {%8,%9}, {%0,%1,%2,%3};"
        : "+f"(d[0]), "+f"(d[1]), "+f"(d[2]), "+f"(d[3])
        : "r"(a[0]), "r"(a[1]), "r"(a[2]), "r"(a[3]), "r"(b[0]), "r"(b[1]));
}
__device__ __forceinline__ unsigned pack_bf16(__nv_bfloat16 a, __nv_bfloat16 b) {
    return ((unsigned)__bfloat16_as_ushort(b) << 16) | (unsigned)__bfloat16_as_ushort(a);
}

// ---------------------------------------------------------------------------
// generic fp32 -> bf16 hi/lo split (grid = n/1024)
// ---------------------------------------------------------------------------
__global__ void split_kernel(const float* __restrict__ src,
                             __nv_bfloat16* __restrict__ h,
                             __nv_bfloat16* __restrict__ l)
{
    size_t i4 = (size_t)blockIdx.x * 256 + threadIdx.x;
    float4 v = *(const float4*)(src + i4 * 4);
    float f[4] = {v.x, v.y, v.z, v.w};
    __nv_bfloat16 hh[4], ll[4];
#pragma unroll
    for (int i = 0; i < 4; i++) {
        hh[i] = __float2bfloat16_rn(f[i]);
        ll[i] = __float2bfloat16_rn(f[i] - __bfloat162float(hh[i]));
    }
    *(uint2*)(h + i4 * 4) = make_uint2(pack_bf16(hh[0], hh[1]), pack_bf16(hh[2], hh[3]));
    *(uint2*)(l + i4 * 4) = make_uint2(pack_bf16(ll[0], ll[1]), pack_bf16(ll[2], ll[3]));
}

__global__ void init_bias_kernel(float* __restrict__ out,
                                 const float* __restrict__ bias)
{
    int idx = blockIdx.x * 256 + threadIdx.x;
    int cj = idx & 63;
    float4 bv = *(const float4*)&bias[cj * 4];
    *(float4*)&out[idx * 4] = bv;
}

// ---------------------------------------------------------------------------
// Projection via warp MMA (bf16 split, 3 terms): out[M,256]=A[M,K]@W[K,256]+b
// MT rows x 256 cols per CTA, 8 warps. gridDim.y = K-split (atomicF=1 path).
// ---------------------------------------------------------------------------
template<int MT>
__global__ __launch_bounds__(256) void proj_mma_kernel(
    const __nv_bfloat16* __restrict__ Ah, const __nv_bfloat16* __restrict__ Al,
    const __nv_bfloat16* __restrict__ Wh, const __nv_bfloat16* __restrict__ Wl,
    const float* __restrict__ bias, int KDIM,
    float* __restrict__ outF, int atomicF,
    __nv_bfloat16* __restrict__ outH, __nv_bfloat16* __restrict__ outL)
{
    constexpr int NRW  = MT / 32;
    constexpr int NCW  = 8 / NRW;
    constexpr int WCOL = 256 / NCW;
    constexpr int NF   = WCOL / 8;
    constexpr int NP   = WCOL / 16;
    constexpr int AST  = 72, WST = 264;

    extern __shared__ char smbuf[];
    __nv_bfloat16* sAh = (__nv_bfloat16*)smbuf;
    __nv_bfloat16* sAl = sAh + MT * AST;
    __nv_bfloat16* sWh = sAl + MT * AST;
    __nv_bfloat16* sWl = sWh + 64 * WST;

    const int t = threadIdx.x, w = t >> 5, l = t & 31;
    const int wr = w / NCW, wc = w % NCW;
    const int aRow = l & 15, aCol = (l >> 4) * 8;
    const int row0 = blockIdx.x * MT;
    const int kd  = KDIM / gridDim.y;
    const int kb0 = blockIdx.y * kd;

    float acc[2][NF][4];
#pragma unroll
    for (int mf = 0; mf < 2; mf++)
#pragma unroll
        for (int nf = 0; nf < NF; nf++)
#pragma unroll
            for (int e = 0; e < 4; e++) acc[mf][nf][e] = 0.f;

    const uint32_t sa_h = smem_u32(sAh), sa_l = smem_u32(sAl);
    const uint32_t sw_h = smem_u32(sWh), sw_l = smem_u32(sWl);

    for (int kb = 0; kb < kd; kb += 64) {
        const int kg = kb0 + kb;
        __syncthreads();
        for (int idx = t; idx < MT * 8; idx += 256) {
            int r = idx >> 3, c = idx & 7;
            *(uint4*)(sAh + r * AST + c * 8) =
                *(const uint4*)(Ah + (size_t)(row0 + r) * KDIM + kg + c * 8);
            *(uint4*)(sAl + r * AST + c * 8) =
                *(const uint4*)(Al + (size_t)(row0 + r) * KDIM + kg + c * 8);
        }
        for (int idx = t; idx < 64 * 32; idx += 256) {
            int r = idx >> 5, c = idx & 31;
            *(uint4*)(sWh + r * WST + c * 8) =
                *(const uint4*)(Wh + (size_t)(kg + r) * 256 + c * 8);
            *(uint4*)(sWl + r * WST + c * 8) =
                *(const uint4*)(Wl + (size_t)(kg + r) * 256 + c * 8);
        }
        __syncthreads();
#pragma unroll
        for (int ks = 0; ks < 4; ks++) {
            uint32_t ah[2][4], al[2][4];
#pragma unroll
            for (int mf = 0; mf < 2; mf++) {
                uint32_t off = (uint32_t)((wr * 32 + mf * 16 + aRow) * AST +
                                          ks * 16 + aCol) * 2;
                ldsm4(ah[mf], sa_h + off);
                ldsm4(al[mf], sa_l + off);
            }
#pragma unroll
            for (int p = 0; p < NP; p++) {
                uint32_t bh[4], bl[4];
                uint32_t off = (uint32_t)((ks * 16 + aRow) * WST +
                                          wc * WCOL + p * 16 + aCol) * 2;
                ldsm4t(bh, sw_h + off);
                ldsm4t(bl, sw_l + off);
#pragma unroll
                for (int mf = 0; mf < 2; mf++)
#pragma unroll
                    for (int sub = 0; sub < 2; sub++) {
                        mma_bf16(acc[mf][p * 2 + sub], ah[mf], &bh[sub * 2]);
                        mma_bf16(acc[mf][p * 2 + sub], ah[mf], &bl[sub * 2]);
                        mma_bf16(acc[mf][p * 2 + sub], al[mf], &bh[sub * 2]);
                    }
            }
        }
    }

#pragma unroll
    for (int mf = 0; mf < 2; mf++)
#pragma unroll
    for (int nf = 0; nf < NF; nf++)
#pragma unroll
    for (int pr = 0; pr < 2; pr++) {
        int r = row0 + wr * 32 + mf * 16 + (l >> 2) + pr * 8;
        int c = wc * WCOL + nf * 8 + (l & 3) * 2;
        float v0 = acc[mf][nf][pr * 2 + 0];
        float v1 = acc[mf][nf][pr * 2 + 1];
        if (atomicF) {
            atomicAdd(outF + (size_t)r * 256 + c,     v0);
            atomicAdd(outF + (size_t)r * 256 + c + 1, v1);
        } else {
            v0 += bias[c]; v1 += bias[c + 1];
            if (outF) *(float2*)(outF + (size_t)r * 256 + c) = make_float2(v0, v1);
            if (outH) {
                __nv_bfloat16 h0 = __float2bfloat16_rn(v0);
                __nv_bfloat16 l0 = __float2bfloat16_rn(v0 - __bfloat162float(h0));
                __nv_bfloat16 h1 = __float2bfloat16_rn(v1);
                __nv_bfloat16 l1 = __float2bfloat16_rn(v1 - __bfloat162float(h1));
                *(uint32_t*)(outH + (size_t)r * 256 + c) = pack_bf16(h0, h1);
                *(uint32_t*)(outL + (size_t)r * 256 + c) = pack_bf16(l0, l1);
            }
        }
    }
}

// ---------------------------------------------------------------------------
// Gram att2 via warp MMA (NT): out[b] = X.X^T, X [256,256] bf16 split.
// CTA 128x128, grid (2,2,16).
// ---------------------------------------------------------------------------
__global__ __launch_bounds__(256) void gram_mma_kernel(
    const __nv_bfloat16* __restrict__ Xh, const __nv_bfloat16* __restrict__ Xl,
    float* __restrict__ out, int N)
{
    constexpr int XST = 72;
    extern __shared__ char smbuf[];
    __nv_bfloat16* sIh = (__nv_bfloat16*)smbuf;
    __nv_bfloat16* sIl = sIh + 128 * XST;
    __nv_bfloat16* sJh = sIl + 128 * XST;
    __nv_bfloat16* sJl = sJh + 128 * XST;

    const int b = blockIdx.z;
    const int i0 = blockIdx.x * 128, j0 = blockIdx.y * 128;
    const int t = threadIdx.x, w = t >> 5, l = t & 31;
    const int wr = w >> 1, wc = w & 1;
    const int aRow = l & 15, aCol = (l >> 4) * 8;
    const int bRow = (l >> 4) * 8 + (l & 7), bCol = ((l >> 3) & 1) * 8;
    const __nv_bfloat16* Xbh = Xh + (size_t)b * N * CCH;
    const __nv_bfloat16* Xbl = Xl + (size_t)b * N * CCH;

    float acc[2][8][4];
#pragma unroll
    for (int mf = 0; mf < 2; mf++)
#pragma unroll
        for (int nf = 0; nf < 8; nf++)
#pragma unroll
            for (int e = 0; e < 4; e++) acc[mf][nf][e] = 0.f;

    const uint32_t si_h = smem_u32(sIh), si_l = smem_u32(sIl);
    const uint32_t sj_h = smem_u32(sJh), sj_l = smem_u32(sJl);

    for (int kb = 0; kb < CCH; kb += 64) {
        __syncthreads();
        for (int idx = t; idx < 128 * 8; idx += 256) {
            int r = idx >> 3, c = idx & 7;
            *(uint4*)(sIh + r * XST + c * 8) =
                *(const uint4*)(Xbh + (size_t)(i0 + r) * CCH + kb + c * 8);
            *(uint4*)(sIl + r * XST + c * 8) =
                *(const uint4*)(Xbl + (size_t)(i0 + r) * CCH + kb + c * 8);
            *(uint4*)(sJh + r * XST + c * 8) =
                *(const uint4*)(Xbh + (size_t)(j0 + r) * CCH + kb + c * 8);
            *(uint4*)(sJl + r * XST + c * 8) =
                *(const uint4*)(Xbl + (size_t)(j0 + r) * CCH + kb + c * 8);
        }
        __syncthreads();
#pragma unroll
        for (int ks = 0; ks < 4; ks++) {
            uint32_t ah[2][4], al[2][4];
#pragma unroll
            for (int mf = 0; mf < 2; mf++) {
                uint32_t off = (uint32_t)((wr * 32 + mf * 16 + aRow) * XST +
                                          ks * 16 + aCol) * 2;
                ldsm4(ah[mf], si_h + off);
                ldsm4(al[mf], si_l + off);
            }
#pragma unroll
            for (int bt = 0; bt < 4; bt++) {
                uint32_t bh[4], bl[4];
                uint32_t off = (uint32_t)((wc * 64 + bt * 16 + bRow) * XST +
                                          ks * 16 + bCol) * 2;
                ldsm4(bh, sj_h + off);
                ldsm4(bl, sj_l + off);
#pragma unroll
                for (int mf = 0; mf < 2; mf++)
#pragma unroll
                    for (int sub = 0; sub < 2; sub++) {
                        mma_bf16(acc[mf][bt * 2 + sub], ah[mf], &bh[sub * 2]);
                        mma_bf16(acc[mf][bt * 2 + sub], ah[mf], &bl[sub * 2]);
                        mma_bf16(acc[mf][bt * 2 + sub], al[mf], &bh[sub * 2]);
                    }
            }
        }
    }

#pragma unroll
    for (int mf = 0; mf < 2; mf++)
#pragma unroll
    for (int nf = 0; nf < 8; nf++)
#pragma unroll
    for (int pr = 0; pr < 2; pr++) {
        int i = i0 + wr * 32 + mf * 16 + (l >> 2) + pr * 8;
        int j = j0 + wc * 64 + nf * 8 + (l & 3) * 2;
        *(float2*)(out + (size_t)b * N * N + (size_t)i * N + j) =
            make_float2(acc[mf][nf][pr * 2 + 0], acc[mf][nf][pr * 2 + 1]);
    }
}

// ---------------------------------------------------------------------------
// Gram 64x64 (att3, fp32 — tiny)
// ---------------------------------------------------------------------------
__global__ __launch_bounds__(256) void attnt_kernel(
    const float* __restrict__ X, float* __restrict__ out, int N)
{
    __shared__ float Ai[32][65];
    __shared__ float Bj[32][65];
    const int b  = blockIdx.z;
    const int i0 = blockIdx.x * 64, j0 = blockIdx.y * 64;
    const int t  = threadIdx.x;
    const int ty = t >> 4, tx = t & 15;
    const int r0 = ty * 4, c0 = tx * 4;
    const float* Xb = X + (size_t)b * N * CCH;

    float acc[4][4] = {};
    for (int k0 = 0; k0 < CCH; k0 += 32) {
#pragma unroll
        for (int i = 0; i < 8; i++) {
            int lin = t + 256 * i;
            int r = lin >> 5, k = lin & 31;
            Ai[k][r] = Xb[(size_t)(i0 + r) * CCH + k0 + k];
            Bj[k][r] = Xb[(size_t)(j0 + r) * CCH + k0 + k];
        }
        __syncthreads();
#pragma unroll
        for (int k = 0; k < 32; k++) {
            float a[4], bb[4];
#pragma unroll
            for (int i = 0; i < 4; i++) a[i]  = Ai[k][r0 + i];
#pragma unroll
            for (int j = 0; j < 4; j++) bb[j] = Bj[k][c0 + j];
#pragma unroll
            for (int i = 0; i < 4; i++)
#pragma unroll
                for (int j = 0; j < 4; j++)
                    acc[i][j] += a[i] * bb[j];
        }
        __syncthreads();
    }
#pragma unroll
    for (int i = 0; i < 4; i++) {
        float4 o = make_float4(acc[i][0], acc[i][1], acc[i][2], acc[i][3]);
        *(float4*)&out[(size_t)b * N * N + (size_t)(i0 + r0 + i) * N + j0 + c0] = o;
    }
}

// ---------------------------------------------------------------------------
// Fused sigmoid-attention via warp MMA (unchanged from round 6)
// ---------------------------------------------------------------------------
#define QSTR 264
#define KSTR 136

#define GEMM2_HALF(OARR) do {                                                  \
    _Pragma("unroll")                                                          \
    for (int kc_ = 0; kc_ < 8; kc_++) {                                        \
        uint32_t a2h[2][4], a2l[2][4];                                         \
        _Pragma("unroll")                                                      \
        for (int mf_ = 0; mf_ < 2; mf_++) {                                    \
            uint32_t off_ = ((wn * 32 + mf_ * 16 + aRow) * KSTR +              \
                             kc_ * 16 + aCol) * 2;                             \
            ldsm4(a2h[mf_], sh0 + off_);                                       \
            ldsm4(a2l[mf_], sl0 + off_);                                       \
        }                                                                      \
        uint32_t b2h[4][2], b2l[4][2];                                         \
        _Pragma("unroll")                                                      \
        for (int bt_ = 0; bt_ < 2; bt_++) {                                    \
            uint32_t off_ = ((kc_ * 16 + aRow) * KSTR +                        \
                             wq * 32 + bt_ * 16 + aCol) * 2;                   \
            uint32_t r4_[4];                                                   \
            ldsm4t(r4_, kh0 + off_);                                           \
            b2h[bt_*2][0]=r4_[0]; b2h[bt_*2][1]=r4_[1];                        \
            b2h[bt_*2+1][0]=r4_[2]; b2h[bt_*2+1][1]=r4_[3];                    \
            ldsm4t(r4_, kl0 + off_);                                           \
            b2l[bt_*2][0]=r4_[0]; b2l[bt_*2][1]=r4_[1];                        \
            b2l[bt_*2+1][0]=r4_[2]; b2l[bt_*2+1][1]=r4_[3];                    \
        }                                                                      \
        _Pragma("unroll")                                                      \
        for (int mf_ = 0; mf_ < 2; mf_++)                                      \
        _Pragma("unroll")                                                      \
        for (int f_ = 0; f_ < 4; f_++) {                                       \
            mma_bf16(OARR[mf_][f_], a2h[mf_], b2h[f_]);                        \
            mma_bf16(OARR[mf_][f_], a2h[mf_], b2l[f_]);                        \
            mma_bf16(OARR[mf_][f_], a2l[mf_], b2h[f_]);                        \
        }                                                                      \
    }                                                                          \
} while (0)

__global__ __launch_bounds__(256, 1) void fused_mma_kernel(
    const __nv_bfloat16* __restrict__ xh, const __nv_bfloat16* __restrict__ xl,
    const float* __restrict__ p1,
    const float* __restrict__ att2, const float* __restrict__ att3,
    const float* __restrict__ pa1, const float* __restrict__ pa2,
    const float* __restrict__ pa3, float* __restrict__ out)
{
    extern __shared__ char smbuf[];
    __nv_bfloat16* Qh = (__nv_bfloat16*)smbuf;
    __nv_bfloat16* Ql = Qh + 64 * QSTR;
    __nv_bfloat16* Kh = Ql + 64 * QSTR;
    __nv_bfloat16* Kl = Kh + 128 * KSTR;
    __nv_bfloat16* Sh = Kl + 128 * KSTR;
    __nv_bfloat16* Sl = Sh + 64 * KSTR;
    float* A2s = (float*)(Sl + 64 * KSTR);
    float* A3s = A2s + 17 * 257;

    const int b  = blockIdx.y;
    const int n0 = blockIdx.x * 64;
    const int t  = threadIdx.x, w = t >> 5, l = t & 31;
    const int wn = w & 1, wq = w >> 1;
    const int aRow = l & 15, aCol = (l >> 4) * 8;
    const int bRow = ((l >> 4) * 8) + (l & 7);
    const int bCol = ((l >> 3) & 1) * 8;

    const __nv_bfloat16* Xh = xh + (size_t)b * N1D * CCH;
    const __nv_bfloat16* Xl = xl + (size_t)b * N1D * CCH;
    const float sa1 = *pa1, sa2 = *pa2, sa3 = *pa3;
    const int r2lo = n0 >> 2, r3lo = n0 >> 4;

#pragma unroll
    for (int i = 0; i < 8; i++) {
        int idx = t + 256 * i;
        int r = idx >> 5, c = idx & 31;
        *(uint4*)(Qh + r * QSTR + c * 8) =
            *(const uint4*)(Xh + (size_t)(n0 + r) * CCH + c * 8);
        *(uint4*)(Ql + r * QSTR + c * 8) =
            *(const uint4*)(Xl + (size_t)(n0 + r) * CCH + c * 8);
    }
    for (int i = t; i < 17 * 256; i += 256) {
        int rr = i >> 8, cc = i & 255;
        A2s[rr * 257 + cc] = att2[((size_t)b * 256 + min(r2lo + rr, 255)) * 256 + cc];
    }
    for (int i = t; i < 5 * 64; i += 256) {
        int rr = i >> 6, cc = i & 63;
        A3s[rr * 65 + cc] = att3[((size_t)b * 64 + min(r3lo + rr, 63)) * 64 + cc];
    }

    const uint32_t qh0 = smem_u32(Qh), ql0 = smem_u32(Ql);
    const uint32_t kh0 = smem_u32(Kh), kl0 = smem_u32(Kl);
    const uint32_t sh0 = smem_u32(Sh), sl0 = smem_u32(Sl);

    const float* R0p[4]; const float* R1p[4];
    const float* S0p[4]; const float* S1p[4];
    float fnv[4], fn3v[4];
#pragma unroll
    for (int rr = 0; rr < 4; rr++) {
        int n = n0 + wn * 32 + (rr >> 1) * 16 + (l >> 2) + (rr & 1) * 8;
        int rn = n >> 2;
        fnv[rr] = (float)(n & 3) * 0.25f;
        R0p[rr] = A2s + (rn - r2lo) * 257;
        R1p[rr] = A2s + (min(rn + 1, 255) - r2lo) * 257;
        int rn3 = n >> 4;
        fn3v[rr] = (float)(n & 15) * 0.0625f;
        S0p[rr] = A3s + (rn3 - r3lo) * 65;
        S1p[rr] = A3s + (min(rn3 + 1, 63) - r3lo) * 65;
    }

    float O0[2][4][4], O1[2][4][4];
#pragma unroll
    for (int mf = 0; mf < 2; mf++)
#pragma unroll
        for (int f = 0; f < 4; f++)
#pragma unroll
            for (int e = 0; e < 4; e++) { O0[mf][f][e] = 0.f; O1[mf][f][e] = 0.f; }

    for (int mt = 0; mt < 8; mt++) {
        const int m0 = mt * 128;
        float S[2][4][4];
#pragma unroll
        for (int mf = 0; mf < 2; mf++)
#pragma unroll
            for (int nf = 0; nf < 4; nf++)
#pragma unroll
                for (int e = 0; e < 4; e++) S[mf][nf][e] = 0.f;

#pragma unroll 1
        for (int h = 0; h < 2; h++) {
            __syncthreads();
#pragma unroll
            for (int i = 0; i < 8; i++) {
                int idx = t + 256 * i;
                int r = idx >> 4, c = idx & 15;
                *(uint4*)(Kh + r * KSTR + c * 8) =
                    *(const uint4*)(Xh + (size_t)(m0 + r) * CCH + h * 128 + c * 8);
                *(uint4*)(Kl + r * KSTR + c * 8) =
                    *(const uint4*)(Xl + (size_t)(m0 + r) * CCH + h * 128 + c * 8);
            }
            __syncthreads();
#pragma unroll
            for (int kc = 0; kc < 8; kc++) {
                uint32_t a1h[2][4], a1l[2][4];
#pragma unroll
                for (int mf = 0; mf < 2; mf++) {
                    uint32_t off = ((wn * 32 + mf * 16 + aRow) * QSTR +
                                    h * 128 + kc * 16 + aCol) * 2;
                    ldsm4(a1h[mf], qh0 + off);
                    ldsm4(a1l[mf], ql0 + off);
                }
                uint32_t b1h[4][2], b1l[4][2];
#pragma unroll
                for (int bt = 0; bt < 2; bt++) {
                    uint32_t off = ((wq * 32 + bt * 16 + bRow) * KSTR +
                                    kc * 16 + bCol) * 2;
                    uint32_t r4[4];
                    ldsm4(r4, kh0 + off);
                    b1h[bt*2][0]=r4[0]; b1h[bt*2][1]=r4[1];
                    b1h[bt*2+1][0]=r4[2]; b1h[bt*2+1][1]=r4[3];
                    ldsm4(r4, kl0 + off);
                    b1l[bt*2][0]=r4[0]; b1l[bt*2][1]=r4[1];
                    b1l[bt*2+1][0]=r4[2]; b1l[bt*2+1][1]=r4[3];
                }
#pragma unroll
                for (int mf = 0; mf < 2; mf++)
#pragma unroll
                for (int nf = 0; nf < 4; nf++) {
                    mma_bf16(S[mf][nf], a1h[mf], b1h[nf]);
                    mma_bf16(S[mf][nf], a1h[mf], b1l[nf]);
                    mma_bf16(S[mf][nf], a1l[mf], b1h[nf]);
                }
            }
        }

#pragma unroll
        for (int mf = 0; mf < 2; mf++)
#pragma unroll
        for (int nf = 0; nf < 4; nf++)
#pragma unroll
        for (int pr = 0; pr < 2; pr++) {
            const int rr = mf * 2 + pr;
            const int row_l = wn * 32 + mf * 16 + (l >> 2) + pr * 8;
            const int col_l = wq * 32 + nf * 8 + (l & 3) * 2;
            const float fn = fnv[rr], fn3 = fn3v[rr];
            const float *R0 = R0p[rr], *R1 = R1p[rr];
            const float *T0 = S0p[rr], *T1 = S1p[rr];
            __nv_bfloat16 hh[2], hl[2];
#pragma unroll
            for (int e = 0; e < 2; e++) {
                int m = m0 + col_l + e;
                float Sv = S[mf][nf][pr * 2 + e];
                int cm = m >> 2;
                float fm = (float)(m & 3) * 0.25f;
                int cm1 = min(cm + 1, 255);
                float v2 = (1.f - fn) * ((1.f - fm) * R0[cm] + fm * R0[cm1]) +
                           fn         * ((1.f - fm) * R1[cm] + fm * R1[cm1]);
                int cm3 = m >> 4;
                float fm3 = (float)(m & 15) * 0.0625f;
                int cm31 = min(cm3 + 1, 63);
                float v3 = (1.f - fn3) * ((1.f - fm3) * T0[cm3] + fm3 * T0[cm31]) +
                           fn3         * ((1.f - fm3) * T1[cm3] + fm3 * T1[cm31]);
                float val = sa1 * Sv + sa2 * v2 + sa3 * v3;
                float sg = 1.0f / (1.0f + __expf(-val));
                hh[e] = __float2bfloat16_rn(sg);
                hl[e] = __float2bfloat16_rn(sg - __bfloat162float(hh[e]));
            }
            *(uint32_t*)&Sh[row_l * KSTR + col_l] = pack_bf16(hh[0], hh[1]);
            *(uint32_t*)&Sl[row_l * KSTR + col_l] = pack_bf16(hl[0], hl[1]);
        }
        __syncthreads();

        GEMM2_HALF(O1);
        __syncthreads();
#pragma unroll
        for (int i = 0; i < 8; i++) {
            int idx = t + 256 * i;
            int r = idx >> 4, c = idx & 15;
            *(uint4*)(Kh + r * KSTR + c * 8) =
                *(const uint4*)(Xh + (size_t)(m0 + r) * CCH + c * 8);
            *(uint4*)(Kl + r * KSTR + c * 8) =
                *(const uint4*)(Xl + (size_t)(m0 + r) * CCH + c * 8);
        }
        __syncthreads();
        GEMM2_HALF(O0);
    }

#pragma unroll
    for (int mf = 0; mf < 2; mf++)
#pragma unroll
    for (int f = 0; f < 4; f++)
#pragma unroll
    for (int pr = 0; pr < 2; pr++) {
        const int n = n0 + wn * 32 + mf * 16 + (l >> 2) + pr * 8;
        const int ch0 = wq * 32 + f * 8 + (l & 3) * 2;
        {
            const size_t o = ((size_t)(b * N1D + n)) * CCH + ch0;
            float2 pv = *(const float2*)(p1 + o);
            *(float2*)(out + o) = make_float2(O0[mf][f][pr*2+0] + pv.x,
                                              O0[mf][f][pr*2+1] + pv.y);
        }
        {
            const size_t o = ((size_t)(b * N1D + n)) * CCH + 128 + ch0;
            float2 pv = *(const float2*)(p1 + o);
            *(float2*)(out + o) = make_float2(O1[mf][f][pr*2+0] + pv.x,
                                              O1[mf][f][pr*2+1] + pv.y);
        }
    }
}

// ---------------------------------------------------------------------------
extern "C" void kernel_launch(void* const* d_in, const int* in_sizes, int n_in,
                              void* d_out, int out_size)
{
    const float* f1 = (const float*)d_in[0];
    const float* f2 = (const float*)d_in[1];
    const float* f3 = (const float*)d_in[2];
    const float* w1 = (const float*)d_in[3];
    const float* b1 = (const float*)d_in[4];
    const float* w2 = (const float*)d_in[5];
    const float* b2 = (const float*)d_in[6];
    const float* w3 = (const float*)d_in[7];
    const float* b3 = (const float*)d_in[8];
    const float* a1 = (const float*)d_in[9];
    const float* a2 = (const float*)d_in[10];
    const float* a3 = (const float*)d_in[11];
    float* out = (float*)d_out;

    float *p1, *x3, *att2, *att3;
    __nv_bfloat16 *x1h, *x1l, *x2h, *x2l;
    __nv_bfloat16 *f1h, *f1l, *f2h, *f2l, *f3h, *f3l;
    __nv_bfloat16 *w1h, *w1l, *w2h, *w2l, *w3h, *w3l;
    cudaGetSymbolAddress((void**)&p1,   g_p1);
    cudaGetSymbolAddress((void**)&x3,   g_x3);
    cudaGetSymbolAddress((void**)&att2, g_att2);
    cudaGetSymbolAddress((void**)&att3, g_att3);
    cudaGetSymbolAddress((void**)&x1h,  g_x1h);
    cudaGetSymbolAddress((void**)&x1l,  g_x1l);
    cudaGetSymbolAddress((void**)&x2h,  g_x2h);
    cudaGetSymbolAddress((void**)&x2l,  g_x2l);
    cudaGetSymbolAddress((void**)&f1h,  g_f1h);
    cudaGetSymbolAddress((void**)&f1l,  g_f1l);
    cudaGetSymbolAddress((void**)&f2h,  g_f2h);
    cudaGetSymbolAddress((void**)&f2l,  g_f2l);
    cudaGetSymbolAddress((void**)&f3h,  g_f3h);
    cudaGetSymbolAddress((void**)&f3l,  g_f3l);
    cudaGetSymbolAddress((void**)&w1h,  g_w1h);
    cudaGetSymbolAddress((void**)&w1l,  g_w1l);
    cudaGetSymbolAddress((void**)&w2h,  g_w2h);
    cudaGetSymbolAddress((void**)&w2l,  g_w2l);
    cudaGetSymbolAddress((void**)&w3h,  g_w3h);
    cudaGetSymbolAddress((void**)&w3l,  g_w3l);

    // input splits
    split_kernel<<<(BATCH * N1D * CCH) / 1024, 256>>>(f1, f1h, f1l);
    split_kernel<<<(BATCH * 256 * 512) / 1024, 256>>>(f2, f2h, f2l);
    split_kernel<<<(BATCH * 64 * 1024) / 1024, 256>>>(f3, f3h, f3l);
    split_kernel<<<(256 * 256)   / 1024, 256>>>(w1, w1h, w1l);
    split_kernel<<<(512 * 256)   / 1024, 256>>>(w2, w2h, w2l);
    split_kernel<<<(1024 * 256)  / 1024, 256>>>(w3, w3h, w3l);

    // x3 bias preinit (proj3 accumulates atomically)
    init_bias_kernel<<<(BATCH * 64 * CCH) / 1024, 256>>>(x3, b3);

    const int smemP128 = (128 * 72 * 2 + 64 * 264 * 2) * 2;
    const int smemP64  = (64  * 72 * 2 + 64 * 264 * 2) * 2;
    cudaFuncSetAttribute(proj_mma_kernel<128>,
                         cudaFuncAttributeMaxDynamicSharedMemorySize, smemP128);
    cudaFuncSetAttribute(proj_mma_kernel<64>,
                         cudaFuncAttributeMaxDynamicSharedMemorySize, smemP64);

    // proj1: p1 fp32 + x1 hi/lo
    proj_mma_kernel<128><<<dim3(128, 1), 256, smemP128>>>(
        f1h, f1l, w1h, w1l, b1, 256, p1, 0, x1h, x1l);
    // proj2: x2 hi/lo only
    proj_mma_kernel<64><<<dim3(64, 1), 256, smemP64>>>(
        f2h, f2l, w2h, w2l, b2, 512, nullptr, 0, x2h, x2l);
    // proj3: fp32 atomic into bias-preinit x3 (K-split 4)
    proj_mma_kernel<64><<<dim3(16, 4), 256, smemP64>>>(
        f3h, f3l, w3h, w3l, b3, 1024, x3, 1, nullptr, nullptr);

    // att2 Gram via MMA
    const int smemG = 4 * 128 * 72 * 2;
    cudaFuncSetAttribute(gram_mma_kernel,
                         cudaFuncAttributeMaxDynamicSharedMemorySize, smemG);
    gram_mma_kernel<<<dim3(2, 2, BATCH), 256, smemG>>>(x2h, x2l, att2, 256);

    // att3 Gram fp32
    attnt_kernel<<<dim3(1, 1, BATCH), 256>>>(x3, att3, 64);

    // fused attention
    const int smemF =
        (64 * QSTR * 2 + 128 * KSTR * 2 + 64 * KSTR * 2) * 2
        + (17 * 257 + 5 * 65) * 4;
    cudaFuncSetAttribute(fused_mma_kernel,
                         cudaFuncAttributeMaxDynamicSharedMemorySize, smemF);
    fused_mma_kernel<<<dim3(16, BATCH), 256, smemF>>>(
        x1h, x1l, p1, att2, att3, a1, a2, a3, out);
}